// round 6
// baseline (speedup 1.0000x reference)
#include <cuda_runtime.h>
#include <cuda_bf16.h>
#include <math.h>

// Problem constants
#define BATCH 64
#define NSEP  6
#define SLEN  256
#define TLEN  64
#define DMODEL 512
#define NHEAD 4
#define DHEAD 128
#define FFDIM 512
#define NLAYER 4
#define IMGDIM 2048

#define MAIN_TOK (BATCH*SLEN)          // 16384
#define HIST_SEQ (BATCH*NSEP)          // 384
#define HIST_TOK (HIST_SEQ*TLEN)       // 24576
#define MAXTOK   HIST_TOK
#define IMG_ELEMS (HIST_SEQ*IMGDIM)    // 786432

// ---------------- scratch (device globals; no allocation allowed) ------------
__device__ float g_x [MAXTOK*DMODEL];
__device__ float g_q [MAXTOK*DMODEL];
__device__ float g_k [MAXTOK*DMODEL];
__device__ float g_v [MAXTOK*DMODEL];
__device__ float g_t2[MAXTOK*DMODEL];
__device__ float g_hidden[BATCH*DMODEL];
__device__ float g_sep[HIST_SEQ*DMODEL];

// split activations
__device__ unsigned short g_xhi [MAXTOK*DMODEL];
__device__ unsigned short g_xlo [MAXTOK*DMODEL];
__device__ unsigned short g_t1hi[MAXTOK*DMODEL];
__device__ unsigned short g_t1lo[MAXTOK*DMODEL];
__device__ unsigned short g_sihi[IMG_ELEMS];
__device__ unsigned short g_silo[IMG_ELEMS];

// Pre-split weights (bf16 hi/lo): 0:Wq 1:Wk 2:Wv 3:Wo 4:W1 5:W2 6:Wsep
#define WTSZ 1048576
__device__ unsigned short g_whi[7*WTSZ];
__device__ unsigned short g_wlo[7*WTSZ];

__device__ __forceinline__ void bsplit(float v, unsigned short& h, unsigned short& l)
{
    __nv_bfloat16 bh = __float2bfloat16_rn(v);
    float r = v - __bfloat162float(bh);
    __nv_bfloat16 bl = __float2bfloat16_rn(r);
    h = __bfloat16_as_ushort(bh);
    l = __bfloat16_as_ushort(bl);
}

// ---------------- one-time split (weights, image input) ----------------------
__global__ void wsplit_kernel(const float* __restrict__ w, unsigned short* __restrict__ hi,
                              unsigned short* __restrict__ lo, int n4)
{
    int i = blockIdx.x * 256 + threadIdx.x;
    if (i >= n4) return;
    float4 v = ((const float4*)w)[i];
    ushort4 h4, l4;
    bsplit(v.x, h4.x, l4.x);
    bsplit(v.y, h4.y, l4.y);
    bsplit(v.z, h4.z, l4.z);
    bsplit(v.w, h4.w, l4.w);
    ((ushort4*)hi)[i] = h4;
    ((ushort4*)lo)[i] = l4;
}

// =====================================================================
// Tensor-core GEMM: C = A[M,K] @ W[K,N] + bias.
// A and W pre-split bf16 hi/lo. 3-term mma (hi*hi + hi*lo + lo*hi).
// Single smem buffer + register prefetch (R4 structure, proven).
// mode 0: fp32 out. mode 1: relu + split bf16 out.
// Requires: M%128==0, N%64==0, K%16==0.
// =====================================================================
#define TBM 128
#define TBN 64
#define TBK 16
#define ASTRIDE 12
#define BSTRIDE 12

__device__ __forceinline__ void mma16816(float* d, const unsigned* a, const unsigned* b)
{
    asm volatile(
        "mma.sync.aligned.m16n8k16.row.col.f32.bf16.bf16.f32 "
        "{%0,%1,%2,%3},{%4,%5,%6,%7},{%8,%9},{%0,%1,%2,%3};"
        : "+f"(d[0]), "+f"(d[1]), "+f"(d[2]), "+f"(d[3])
        : "r"(a[0]), "r"(a[1]), "r"(a[2]), "r"(a[3]), "r"(b[0]), "r"(b[1]));
}

__global__ __launch_bounds__(256) void gemm_mma(
    const unsigned short* __restrict__ Ahi, const unsigned short* __restrict__ Alo,
    const unsigned short* __restrict__ Whi, const unsigned short* __restrict__ Wlo,
    const float* __restrict__ bias, float* __restrict__ Cf,
    unsigned short* __restrict__ Chi, unsigned short* __restrict__ Clo,
    int M, int N, int K, int mode)
{
    __shared__ unsigned As_hi[TBM * ASTRIDE];
    __shared__ unsigned As_lo[TBM * ASTRIDE];
    __shared__ unsigned Bs_hi[TBN * BSTRIDE];
    __shared__ unsigned Bs_lo[TBN * BSTRIDE];

    int tid  = threadIdx.x;
    int warp = tid >> 5, lane = tid & 31;
    int wm = warp & 1;
    int wn = warp >> 1;
    int g = lane >> 2, c = lane & 3;

    int brow = blockIdx.y * TBM;
    int bcol = blockIdx.x * TBN;

    float acc[4][2][4];
    #pragma unroll
    for (int mt = 0; mt < 4; mt++)
        #pragma unroll
        for (int nt = 0; nt < 2; nt++)
            #pragma unroll
            for (int i = 0; i < 4; i++) acc[mt][nt][i] = 0.f;

    // load mappings
    int a_row0 = tid >> 2, a_kq = (tid & 3) << 2;      // rows a_row0, a_row0+64; 4 k-elems
    int b_k = tid >> 4, b_nq = tid & 15;

    const unsigned short* ah0p = Ahi + (size_t)(brow + a_row0) * K + a_kq;
    const unsigned short* ah1p = Ahi + (size_t)(brow + a_row0 + 64) * K + a_kq;
    const unsigned short* al0p = Alo + (size_t)(brow + a_row0) * K + a_kq;
    const unsigned short* al1p = Alo + (size_t)(brow + a_row0 + 64) * K + a_kq;
    const unsigned short* bhp = Whi + (size_t)b_k * N + bcol + 4 * b_nq;
    const unsigned short* blp = Wlo + (size_t)b_k * N + bcol + 4 * b_nq;

    int abase  = a_row0 * ASTRIDE + (a_kq >> 1);
    int abase1 = (a_row0 + 64) * ASTRIDE + (a_kq >> 1);

    // prologue: fetch tile 0 into registers
    uint2 rah0 = *(const uint2*)(ah0p);
    uint2 rah1 = *(const uint2*)(ah1p);
    uint2 ral0 = *(const uint2*)(al0p);
    uint2 ral1 = *(const uint2*)(al1p);
    ushort4 rbh = *(const ushort4*)(bhp);
    ushort4 rbl = *(const ushort4*)(blp);

    for (int k0 = 0; k0 < K; k0 += TBK) {
        // ---- store staged tile to smem ----
        As_hi[abase] = rah0.x; As_hi[abase+1] = rah0.y;
        As_hi[abase1] = rah1.x; As_hi[abase1+1] = rah1.y;
        As_lo[abase] = ral0.x; As_lo[abase+1] = ral0.y;
        As_lo[abase1] = ral1.x; As_lo[abase1+1] = ral1.y;
        {
            unsigned short* bh16 = (unsigned short*)Bs_hi;
            unsigned short* bl16 = (unsigned short*)Bs_lo;
            int n0 = 4 * b_nq;
            bh16[(n0+0)*(2*BSTRIDE) + b_k] = rbh.x; bl16[(n0+0)*(2*BSTRIDE) + b_k] = rbl.x;
            bh16[(n0+1)*(2*BSTRIDE) + b_k] = rbh.y; bl16[(n0+1)*(2*BSTRIDE) + b_k] = rbl.y;
            bh16[(n0+2)*(2*BSTRIDE) + b_k] = rbh.z; bl16[(n0+2)*(2*BSTRIDE) + b_k] = rbl.z;
            bh16[(n0+3)*(2*BSTRIDE) + b_k] = rbh.w; bl16[(n0+3)*(2*BSTRIDE) + b_k] = rbl.w;
        }
        __syncthreads();

        // ---- prefetch next tile (latency hidden by mma chain below) ----
        int kn = k0 + TBK;
        if (kn < K) {
            rah0 = *(const uint2*)(ah0p + kn);
            rah1 = *(const uint2*)(ah1p + kn);
            ral0 = *(const uint2*)(al0p + kn);
            ral1 = *(const uint2*)(al1p + kn);
            rbh = *(const ushort4*)(bhp + (size_t)kn * N);
            rbl = *(const ushort4*)(blp + (size_t)kn * N);
        }

        // ---- compute ----
        unsigned bhf[2][2], blf[2][2];
        #pragma unroll
        for (int nt = 0; nt < 2; nt++) {
            int n = wn * 16 + nt * 8 + g;
            bhf[nt][0] = Bs_hi[n * BSTRIDE + c];
            bhf[nt][1] = Bs_hi[n * BSTRIDE + 4 + c];
            blf[nt][0] = Bs_lo[n * BSTRIDE + c];
            blf[nt][1] = Bs_lo[n * BSTRIDE + 4 + c];
        }
        #pragma unroll
        for (int mt = 0; mt < 4; mt++) {
            int r0 = wm * 64 + mt * 16 + g;
            unsigned ah[4], al[4];
            ah[0] = As_hi[r0 * ASTRIDE + c];
            ah[1] = As_hi[(r0 + 8) * ASTRIDE + c];
            ah[2] = As_hi[r0 * ASTRIDE + 4 + c];
            ah[3] = As_hi[(r0 + 8) * ASTRIDE + 4 + c];
            al[0] = As_lo[r0 * ASTRIDE + c];
            al[1] = As_lo[(r0 + 8) * ASTRIDE + c];
            al[2] = As_lo[r0 * ASTRIDE + 4 + c];
            al[3] = As_lo[(r0 + 8) * ASTRIDE + 4 + c];
            #pragma unroll
            for (int nt = 0; nt < 2; nt++) {
                mma16816(acc[mt][nt], ah, bhf[nt]);
                mma16816(acc[mt][nt], ah, blf[nt]);
                mma16816(acc[mt][nt], al, bhf[nt]);
            }
        }
        __syncthreads();
    }

    // ---- epilogue ----
    #pragma unroll
    for (int mt = 0; mt < 4; mt++) {
        int row = brow + wm * 64 + mt * 16 + g;
        #pragma unroll
        for (int nt = 0; nt < 2; nt++) {
            int col = bcol + wn * 16 + nt * 8 + 2 * c;
            float2 bs = *(const float2*)(bias + col);
            float v0 = acc[mt][nt][0] + bs.x;
            float v1 = acc[mt][nt][1] + bs.y;
            float v2 = acc[mt][nt][2] + bs.x;
            float v3 = acc[mt][nt][3] + bs.y;
            if (mode == 0) {
                *(float2*)(Cf + (size_t)row * N + col)       = make_float2(v0, v1);
                *(float2*)(Cf + (size_t)(row + 8) * N + col) = make_float2(v2, v3);
            } else {
                v0 = fmaxf(v0, 0.f); v1 = fmaxf(v1, 0.f);
                v2 = fmaxf(v2, 0.f); v3 = fmaxf(v3, 0.f);
                unsigned short h, l;
                unsigned ph, pl;
                bsplit(v0, h, l); ph = h; pl = l;
                bsplit(v1, h, l); ph |= (unsigned)h << 16; pl |= (unsigned)l << 16;
                *(unsigned*)(Chi + (size_t)row * N + col) = ph;
                *(unsigned*)(Clo + (size_t)row * N + col) = pl;
                bsplit(v2, h, l); ph = h; pl = l;
                bsplit(v3, h, l); ph |= (unsigned)h << 16; pl |= (unsigned)l << 16;
                *(unsigned*)(Chi + (size_t)(row + 8) * N + col) = ph;
                *(unsigned*)(Clo + (size_t)(row + 8) * N + col) = pl;
            }
        }
    }
}

// =====================================================================
// Attention: block per (seq m, head h, 64-row q-tile), 256 threads.
// Output written as split bf16 (feeds Wo GEMM only).
// =====================================================================
#define QT 64
#define KC 64
#define QSTR 129
#define KSTR 129
#define VSTR 132

__global__ __launch_bounds__(256) void attn2_kernel(
    const float* __restrict__ q, const float* __restrict__ k,
    const float* __restrict__ v,
    unsigned short* __restrict__ ohi, unsigned short* __restrict__ olo,
    const int* __restrict__ lens, int Tt, int nQT)
{
    extern __shared__ float sm[];
    float* Qs  = sm;
    float* KVs = Qs + QT * QSTR;
    float* SC  = KVs + KC * VSTR;

    int tid = threadIdx.x;
    int b = blockIdx.x;
    int qt  = b % nQT; int rem = b / nQT;
    int h = rem % NHEAD; int m = rem / NHEAD;
    int q0 = qt * QT;
    int sstr = Tt + 1;

    int valid = Tt;
    if (lens) { int l = lens[m]; valid = l > 1 ? l : 1; }

    // ---- load Q tile ----
    const float* qbase = q + ((size_t)m * Tt + q0) * DMODEL + h * DHEAD;
    for (int i = tid; i < QT * (DHEAD/4); i += 256) {
        int row = i >> 5, c4 = i & 31;
        float4 vq = *(const float4*)(qbase + (size_t)row * DMODEL + 4 * c4);
        float* dst = Qs + row * QSTR + 4 * c4;
        dst[0] = vq.x; dst[1] = vq.y; dst[2] = vq.z; dst[3] = vq.w;
    }

    // ---- phase 1: raw scores ----
    int tq = (tid >> 4) << 2;
    int tk = (tid & 15) << 2;
    for (int kc = 0; kc < Tt; kc += KC) {
        __syncthreads();
        const float* kbase = k + ((size_t)m * Tt + kc) * DMODEL + h * DHEAD;
        for (int i = tid; i < KC * (DHEAD/4); i += 256) {
            int row = i >> 5, c4 = i & 31;
            float4 vk = *(const float4*)(kbase + (size_t)row * DMODEL + 4 * c4);
            float* dst = KVs + row * KSTR + 4 * c4;
            dst[0] = vk.x; dst[1] = vk.y; dst[2] = vk.z; dst[3] = vk.w;
        }
        __syncthreads();

        float acc[4][4];
        #pragma unroll
        for (int i = 0; i < 4; i++)
            #pragma unroll
            for (int j = 0; j < 4; j++) acc[i][j] = 0.f;

        const float* qp0 = Qs + (tq + 0) * QSTR;
        const float* qp1 = Qs + (tq + 1) * QSTR;
        const float* qp2 = Qs + (tq + 2) * QSTR;
        const float* qp3 = Qs + (tq + 3) * QSTR;
        const float* kp0 = KVs + (tk + 0) * KSTR;
        const float* kp1 = KVs + (tk + 1) * KSTR;
        const float* kp2 = KVs + (tk + 2) * KSTR;
        const float* kp3 = KVs + (tk + 3) * KSTR;

        #pragma unroll 4
        for (int d = 0; d < DHEAD; d++) {
            float qa[4] = { qp0[d], qp1[d], qp2[d], qp3[d] };
            float kb[4] = { kp0[d], kp1[d], kp2[d], kp3[d] };
            #pragma unroll
            for (int i = 0; i < 4; i++)
                #pragma unroll
                for (int j = 0; j < 4; j++)
                    acc[i][j] += qa[i] * kb[j];
        }
        #pragma unroll
        for (int i = 0; i < 4; i++)
            #pragma unroll
            for (int j = 0; j < 4; j++)
                SC[(tq + i) * sstr + kc + tk + j] = acc[i][j];
    }
    __syncthreads();

    // ---- phase 2: softmax per row ----
    {
        int warp = tid >> 5, lane = tid & 31;
        const float scale = 0.08838834764831845f;
        for (int rr = 0; rr < 8; rr++) {
            float* row = SC + (warp * 8 + rr) * sstr;
            float mx = -1e30f;
            for (int j = lane; j < Tt; j += 32) {
                float s = (j < valid) ? row[j] * scale : -1e9f;
                row[j] = s;
                mx = fmaxf(mx, s);
            }
            #pragma unroll
            for (int o = 16; o; o >>= 1) mx = fmaxf(mx, __shfl_xor_sync(0xffffffffu, mx, o));
            float sum = 0.f;
            for (int j = lane; j < Tt; j += 32) {
                float e = __expf(row[j] - mx);
                row[j] = e;
                sum += e;
            }
            #pragma unroll
            for (int o = 16; o; o >>= 1) sum += __shfl_xor_sync(0xffffffffu, sum, o);
            float inv = 1.f / sum;
            for (int j = lane; j < Tt; j += 32) row[j] *= inv;
        }
    }

    // ---- phase 3: P @ V ----
    int tqg = (tid >> 4) << 2;
    int td  = (tid & 15) << 3;
    float cacc[4][8];
    #pragma unroll
    for (int i = 0; i < 4; i++)
        #pragma unroll
        for (int j = 0; j < 8; j++) cacc[i][j] = 0.f;

    for (int kc = 0; kc < Tt; kc += KC) {
        __syncthreads();
        const float* vbase = v + ((size_t)m * Tt + kc) * DMODEL + h * DHEAD;
        for (int i = tid; i < KC * (DHEAD/4); i += 256) {
            int row = i >> 5, c4 = i & 31;
            float4 vv = *(const float4*)(vbase + (size_t)row * DMODEL + 4 * c4);
            *(float4*)(KVs + row * VSTR + 4 * c4) = vv;
        }
        __syncthreads();

        const float* pp0 = SC + (tqg + 0) * sstr + kc;
        const float* pp1 = SC + (tqg + 1) * sstr + kc;
        const float* pp2 = SC + (tqg + 2) * sstr + kc;
        const float* pp3 = SC + (tqg + 3) * sstr + kc;
        #pragma unroll 2
        for (int kk = 0; kk < KC; kk++) {
            float p[4] = { pp0[kk], pp1[kk], pp2[kk], pp3[kk] };
            float4 v0 = *(const float4*)(KVs + kk * VSTR + td);
            float4 v1 = *(const float4*)(KVs + kk * VSTR + td + 4);
            float vv[8] = { v0.x, v0.y, v0.z, v0.w, v1.x, v1.y, v1.z, v1.w };
            #pragma unroll
            for (int i = 0; i < 4; i++)
                #pragma unroll
                for (int j = 0; j < 8; j++)
                    cacc[i][j] += p[i] * vv[j];
        }
    }

    // ---- store ctx as split bf16 ----
    size_t obase = ((size_t)m * Tt + q0) * DMODEL + h * DHEAD;
    #pragma unroll
    for (int i = 0; i < 4; i++) {
        size_t off = obase + (size_t)(tqg + i) * DMODEL + td;
        #pragma unroll
        for (int j = 0; j < 8; j += 2) {
            unsigned short h0, l0, h1, l1;
            bsplit(cacc[i][j], h0, l0);
            bsplit(cacc[i][j+1], h1, l1);
            *(unsigned*)(ohi + off + j) = (unsigned)h0 | ((unsigned)h1 << 16);
            *(unsigned*)(olo + off + j) = (unsigned)l0 | ((unsigned)l1 << 16);
        }
    }
}

// ---------------- residual add + LayerNorm (+ split emit) -------------------
__global__ void add_ln_kernel(const float* __restrict__ x, const float* __restrict__ y,
                              const float* __restrict__ g, const float* __restrict__ b,
                              float* __restrict__ out,
                              unsigned short* __restrict__ ohi, unsigned short* __restrict__ olo)
{
    int t = blockIdx.x, tid = threadIdx.x;
    const float* xr = x + (size_t)t * DMODEL;
    const float* yr = y + (size_t)t * DMODEL;
    int lane = tid & 31, warp = tid >> 5;
    __shared__ float red[4];

    float h[4];
    float s = 0.f;
    #pragma unroll
    for (int i = 0; i < 4; i++) { int d = tid + i * 128; h[i] = xr[d] + yr[d]; s += h[i]; }
    #pragma unroll
    for (int o = 16; o; o >>= 1) s += __shfl_xor_sync(0xffffffffu, s, o);
    if (lane == 0) red[warp] = s;
    __syncthreads();
    s = red[0] + red[1] + red[2] + red[3];
    float mu = s * (1.f / DMODEL);

    float vs = 0.f;
    #pragma unroll
    for (int i = 0; i < 4; i++) { float dl = h[i] - mu; vs += dl * dl; }
    #pragma unroll
    for (int o = 16; o; o >>= 1) vs += __shfl_xor_sync(0xffffffffu, vs, o);
    __syncthreads();
    if (lane == 0) red[warp] = vs;
    __syncthreads();
    vs = (red[0] + red[1] + red[2] + red[3]) * (1.f / DMODEL);
    float invstd = rsqrtf(vs + 1e-5f);

    float* orow = out + (size_t)t * DMODEL;
    unsigned short* hrow = ohi + (size_t)t * DMODEL;
    unsigned short* lrow = olo + (size_t)t * DMODEL;
    #pragma unroll
    for (int i = 0; i < 4; i++) {
        int d = tid + i * 128;
        float val = (h[i] - mu) * invstd * g[d] + b[d];
        orow[d] = val;
        unsigned short hh, ll;
        bsplit(val, hh, ll);
        hrow[d] = hh;
        lrow[d] = ll;
    }
}

// ---------------- embedding + positional encoding ---------------------------
__device__ __forceinline__ float pe_val(int pos, int d)
{
    int i2 = d & ~1;
    float div = expf((float)i2 * (-9.210340371976184f / (float)DMODEL));
    float ang = (float)pos * div;
    return (d & 1) ? cosf(ang) : sinf(ang);
}

__global__ void embed_kernel(const int* __restrict__ ids, const float* __restrict__ emb,
                             float* __restrict__ x,
                             unsigned short* __restrict__ xhi, unsigned short* __restrict__ xlo,
                             int seqlen)
{
    int tok = blockIdx.x;
    int pos = tok % seqlen;
    int id = ids[tok];
    const float* erow = emb + (size_t)id * DMODEL;
    float* xrow = x + (size_t)tok * DMODEL;
    unsigned short* hrow = xhi + (size_t)tok * DMODEL;
    unsigned short* lrow = xlo + (size_t)tok * DMODEL;
    for (int d = threadIdx.x; d < DMODEL; d += 128) {
        float val = erow[d] + pe_val(pos, d);
        xrow[d] = val;
        unsigned short hh, ll;
        bsplit(val, hh, ll);
        hrow[d] = hh;
        lrow[d] = ll;
    }
}

// ---------------- small epilogue kernels -------------------------------------
__global__ void copy_hidden_kernel(const float* __restrict__ x, float* __restrict__ hid)
{
    int b = blockIdx.x;
    const float* src = x + ((size_t)(b * SLEN + SLEN - 1)) * DMODEL;
    for (int d = threadIdx.x; d < DMODEL; d += 128)
        hid[b * DMODEL + d] = src[d];
}

__global__ void gather_add_kernel(const float* __restrict__ hx, const int* __restrict__ lens,
                                  float* __restrict__ sep)
{
    int r = blockIdx.x;
    int len = lens[r];
    if (len <= 0) return;
    const float* src = hx + ((size_t)(r * TLEN + len - 1)) * DMODEL;
    for (int d = threadIdx.x; d < DMODEL; d += 128)
        sep[(size_t)r * DMODEL + d] += src[d];
}

__global__ void final_kernel(const float* __restrict__ sep, const float* __restrict__ hidden,
                             const int* __restrict__ normalize, float* __restrict__ out)
{
    int r = blockIdx.x;
    int b = r / NSEP;
    int tid = threadIdx.x;
    int lane = tid & 31, warp = tid >> 5;
    int norm = *normalize;

    __shared__ float sbuf[DMODEL];
    __shared__ float red[4];

    for (int d = tid; d < DMODEL; d += 128) {
        float v = sep[(size_t)r * DMODEL + d];
        if (norm) v = fmaxf(v, 0.f);
        sbuf[d] = v;
    }
    __syncthreads();

    float scale = 1.f;
    if (norm) {
        float ss = 0.f;
        for (int d = tid; d < DMODEL; d += 128) ss += sbuf[d] * sbuf[d];
        #pragma unroll
        for (int o = 16; o; o >>= 1) ss += __shfl_xor_sync(0xffffffffu, ss, o);
        if (lane == 0) red[warp] = ss;
        __syncthreads();
        ss = red[0] + red[1] + red[2] + red[3];
        float nrm = sqrtf(ss);
        scale = 1.f / fmaxf(nrm, 1e-12f);
        __syncthreads();
    }

    float dp = 0.f;
    for (int d = tid; d < DMODEL; d += 128)
        dp += sbuf[d] * scale * hidden[(size_t)b * DMODEL + d];
    #pragma unroll
    for (int o = 16; o; o >>= 1) dp += __shfl_xor_sync(0xffffffffu, dp, o);
    if (lane == 0) red[warp] = dp;
    __syncthreads();
    if (tid == 0) out[r] = red[0] + red[1] + red[2] + red[3];
}

// ---------------- host side ---------------------------------------------------
static void gemm_f32(const unsigned short* Ahi, const unsigned short* Alo,
                     const unsigned short* Whi, const unsigned short* Wlo,
                     const float* bias, float* C, int M, int N, int K)
{
    dim3 grid(N / TBN, M / TBM);
    gemm_mma<<<grid, 256>>>(Ahi, Alo, Whi, Wlo, bias, C, nullptr, nullptr, M, N, K, 0);
}

static void gemm_split(const unsigned short* Ahi, const unsigned short* Alo,
                       const unsigned short* Whi, const unsigned short* Wlo,
                       const float* bias, unsigned short* Chi, unsigned short* Clo,
                       int M, int N, int K)
{
    dim3 grid(N / TBN, M / TBM);
    gemm_mma<<<grid, 256>>>(Ahi, Alo, Whi, Wlo, bias, nullptr, Chi, Clo, M, N, K, 1);
}

struct Bufs {
    float *x, *q, *k, *v, *t2, *hid, *sep;
    unsigned short *xhi, *xlo, *t1hi, *t1lo, *sihi, *silo, *whi, *wlo;
};

struct EncParams {
    const unsigned short *whi, *wlo;
    const float *bq, *bk, *bv, *bo;
    const float *ln1g, *ln1b, *b1, *b2, *ln2g, *ln2b;
};

static void launch_attn(const float* q, const float* k, const float* v,
                        unsigned short* ohi, unsigned short* olo,
                        const int* lens, int M, int Tt)
{
    int nQT = Tt / QT;
    int grid = M * NHEAD * nQT;
    size_t smem = (size_t)(QT * QSTR + KC * VSTR + QT * (Tt + 1)) * sizeof(float);
    attn2_kernel<<<grid, 256, smem>>>(q, k, v, ohi, olo, lens, Tt, nQT);
}

static void run_encoder(Bufs& bb, const EncParams& p, const int* lens, int M, int Tt)
{
    int ntok = M * Tt;
    const int LW = DMODEL * DMODEL;
    for (int l = 0; l < NLAYER; l++) {
        const unsigned short* wq_h = p.whi + 0*WTSZ + (size_t)l * LW;
        const unsigned short* wq_l = p.wlo + 0*WTSZ + (size_t)l * LW;
        const unsigned short* wk_h = p.whi + 1*WTSZ + (size_t)l * LW;
        const unsigned short* wk_l = p.wlo + 1*WTSZ + (size_t)l * LW;
        const unsigned short* wv_h = p.whi + 2*WTSZ + (size_t)l * LW;
        const unsigned short* wv_l = p.wlo + 2*WTSZ + (size_t)l * LW;
        const unsigned short* wo_h = p.whi + 3*WTSZ + (size_t)l * LW;
        const unsigned short* wo_l = p.wlo + 3*WTSZ + (size_t)l * LW;
        const unsigned short* w1_h = p.whi + 4*WTSZ + (size_t)l * LW;
        const unsigned short* w1_l = p.wlo + 4*WTSZ + (size_t)l * LW;
        const unsigned short* w2_h = p.whi + 5*WTSZ + (size_t)l * LW;
        const unsigned short* w2_l = p.wlo + 5*WTSZ + (size_t)l * LW;

        gemm_f32(bb.xhi, bb.xlo, wq_h, wq_l, p.bq + l * DMODEL, bb.q, ntok, DMODEL, DMODEL);
        gemm_f32(bb.xhi, bb.xlo, wk_h, wk_l, p.bk + l * DMODEL, bb.k, ntok, DMODEL, DMODEL);
        gemm_f32(bb.xhi, bb.xlo, wv_h, wv_l, p.bv + l * DMODEL, bb.v, ntok, DMODEL, DMODEL);

        launch_attn(bb.q, bb.k, bb.v, bb.t1hi, bb.t1lo, lens, M, Tt);

        gemm_f32(bb.t1hi, bb.t1lo, wo_h, wo_l, p.bo + l * DMODEL, bb.t2, ntok, DMODEL, DMODEL);
        add_ln_kernel<<<ntok, 128>>>(bb.x, bb.t2, p.ln1g + l * DMODEL, p.ln1b + l * DMODEL,
                                     bb.x, bb.xhi, bb.xlo);

        gemm_split(bb.xhi, bb.xlo, w1_h, w1_l, p.b1 + l * FFDIM, bb.t1hi, bb.t1lo,
                   ntok, FFDIM, DMODEL);
        gemm_f32(bb.t1hi, bb.t1lo, w2_h, w2_l, p.b2 + l * DMODEL, bb.t2, ntok, DMODEL, FFDIM);
        add_ln_kernel<<<ntok, 128>>>(bb.x, bb.t2, p.ln2g + l * DMODEL, p.ln2b + l * DMODEL,
                                     bb.x, bb.xhi, bb.xlo);
    }
}

extern "C" void kernel_launch(void* const* d_in, const int* in_sizes, int n_in,
                              void* d_out, int out_size)
{
    const int*   segment    = (const int*)  d_in[0];
    const int*   prev_hist  = (const int*)  d_in[1];
    const int*   hist_len   = (const int*)  d_in[2];
    const float* sep_img    = (const float*)d_in[3];
    const int*   normalize  = (const int*)  d_in[4];
    const float* embedding  = (const float*)d_in[5];

    const float* Wq   = (const float*)d_in[6];  const float* bq   = (const float*)d_in[7];
    const float* Wk   = (const float*)d_in[8];  const float* bk   = (const float*)d_in[9];
    const float* Wv   = (const float*)d_in[10]; const float* bv   = (const float*)d_in[11];
    const float* Wo   = (const float*)d_in[12]; const float* bo   = (const float*)d_in[13];
    const float* ln1g = (const float*)d_in[14]; const float* ln1b = (const float*)d_in[15];
    const float* W1   = (const float*)d_in[16]; const float* b1   = (const float*)d_in[17];
    const float* W2   = (const float*)d_in[18]; const float* b2   = (const float*)d_in[19];
    const float* ln2g = (const float*)d_in[20]; const float* ln2b = (const float*)d_in[21];
    const float* Wsep = (const float*)d_in[22];
    const float* bsep = (const float*)d_in[23];

    Bufs bb;
    cudaGetSymbolAddress((void**)&bb.x,    g_x);
    cudaGetSymbolAddress((void**)&bb.q,    g_q);
    cudaGetSymbolAddress((void**)&bb.k,    g_k);
    cudaGetSymbolAddress((void**)&bb.v,    g_v);
    cudaGetSymbolAddress((void**)&bb.t2,   g_t2);
    cudaGetSymbolAddress((void**)&bb.hid,  g_hidden);
    cudaGetSymbolAddress((void**)&bb.sep,  g_sep);
    cudaGetSymbolAddress((void**)&bb.xhi,  g_xhi);
    cudaGetSymbolAddress((void**)&bb.xlo,  g_xlo);
    cudaGetSymbolAddress((void**)&bb.t1hi, g_t1hi);
    cudaGetSymbolAddress((void**)&bb.t1lo, g_t1lo);
    cudaGetSymbolAddress((void**)&bb.sihi, g_sihi);
    cudaGetSymbolAddress((void**)&bb.silo, g_silo);
    cudaGetSymbolAddress((void**)&bb.whi,  g_whi);
    cudaGetSymbolAddress((void**)&bb.wlo,  g_wlo);

    cudaFuncSetAttribute(attn2_kernel, cudaFuncAttributeMaxDynamicSharedMemorySize, 140 * 1024);

    // ---- pre-split weights + image input ----
    {
        const float* srcs[7] = { Wq, Wk, Wv, Wo, W1, W2, Wsep };
        for (int t = 0; t < 7; t++) {
            int n4 = WTSZ / 4;
            wsplit_kernel<<<(n4 + 255) / 256, 256>>>(srcs[t], bb.whi + (size_t)t * WTSZ,
                                                     bb.wlo + (size_t)t * WTSZ, n4);
        }
        int n4 = IMG_ELEMS / 4;
        wsplit_kernel<<<(n4 + 255) / 256, 256>>>(sep_img, bb.sihi, bb.silo, n4);
    }

    EncParams p;
    p.whi = bb.whi; p.wlo = bb.wlo;
    p.bq = bq; p.bk = bk; p.bv = bv; p.bo = bo;
    p.ln1g = ln1g; p.ln1b = ln1b; p.b1 = b1; p.b2 = b2; p.ln2g = ln2g; p.ln2b = ln2b;

    // ---- main encoder ----
    embed_kernel<<<MAIN_TOK, 128>>>(segment, embedding, bb.x, bb.xhi, bb.xlo, SLEN);
    run_encoder(bb, p, nullptr, BATCH, SLEN);
    copy_hidden_kernel<<<BATCH, 128>>>(bb.x, bb.hid);

    // ---- separate image projection: (384,2048) @ (2048,512) + b ----
    gemm_f32(bb.sihi, bb.silo, bb.whi + (size_t)6 * WTSZ, bb.wlo + (size_t)6 * WTSZ,
             bsep, bb.sep, HIST_SEQ, FFDIM, IMGDIM);

    // ---- history encoder ----
    embed_kernel<<<HIST_TOK, 128>>>(prev_hist, embedding, bb.x, bb.xhi, bb.xlo, TLEN);
    run_encoder(bb, p, hist_len, HIST_SEQ, TLEN);

    // ---- gather last hidden, add to sep, normalize + dot ----
    gather_add_kernel<<<HIST_SEQ, 128>>>(bb.x, hist_len, bb.sep);
    final_kernel<<<HIST_SEQ, 128>>>(bb.sep, bb.hid, normalize, (float*)d_out);
}

// round 7
// speedup vs baseline: 1.4913x; 1.4913x over previous
#include <cuda_runtime.h>
#include <math.h>

// Problem constants
#define BATCH 64
#define NSEP  6
#define SLEN  256
#define TLEN  64
#define DMODEL 512
#define NHEAD 4
#define DHEAD 128
#define FFDIM 512
#define NLAYER 4
#define IMGDIM 2048

#define MAIN_TOK (BATCH*SLEN)          // 16384
#define HIST_SEQ (BATCH*NSEP)          // 384
#define HIST_TOK (HIST_SEQ*TLEN)       // 24576
#define MAXTOK   HIST_TOK

// ---------------- scratch (device globals; no allocation allowed) ------------
__device__ float g_x [MAXTOK*DMODEL];
__device__ float g_q [MAXTOK*DMODEL];
__device__ float g_k [MAXTOK*DMODEL];
__device__ float g_v [MAXTOK*DMODEL];
__device__ float g_t1[MAXTOK*DMODEL];
__device__ float g_t2[MAXTOK*DMODEL];
__device__ float g_hidden[BATCH*DMODEL];
__device__ float g_sep[HIST_SEQ*DMODEL];

// Pre-rounded (tf32/rna) weights, stored as fp32 bit patterns:
// 0:Wq 1:Wk 2:Wv 3:Wo 4:W1 5:W2 6:Wsep   (all 1,048,576 elems)
#define WTSZ 1048576
__device__ float g_wr[7*WTSZ];

__device__ __forceinline__ float tf32r(float x)
{
    unsigned u;
    asm("cvt.rna.tf32.f32 %0, %1;" : "=r"(u) : "f"(x));
    return __uint_as_float(u);
}

// ---------------- one-time weight rounding -----------------------------------
__global__ void wround_kernel(const float* __restrict__ w, float* __restrict__ o, int n4)
{
    int i = blockIdx.x * 256 + threadIdx.x;
    if (i >= n4) return;
    float4 v = ((const float4*)w)[i];
    v.x = tf32r(v.x); v.y = tf32r(v.y); v.z = tf32r(v.z); v.w = tf32r(v.w);
    ((float4*)o)[i] = v;
}

// =====================================================================
// tf32 tensor-core GEMM: C = A[M,K] @ W[K,N] + bias, optional ReLU.
// W pre-rounded to tf32; A rounded (rna) at smem staging.
// Block tile 128x128x16, 128 threads (4 warps, 2x2), warp tile 64x64.
// mma.m16n8k8.tf32: per warp per ktile 4mt x 8nt x 2ksteps = 64 mma.
// Requires: M%128==0, N%128==0, K%16==0 (all call sites satisfy).
// =====================================================================
#define TBM 128
#define TBN 128
#define TBK 16
#define SSTR 20    // float stride per row: 16 data + 4 pad (16B-aligned, conflict-free frags)

__device__ __forceinline__ void mma1688(float* d, const unsigned* a, const unsigned* b)
{
    asm volatile(
        "mma.sync.aligned.m16n8k8.row.col.f32.tf32.tf32.f32 "
        "{%0,%1,%2,%3},{%4,%5,%6,%7},{%8,%9},{%0,%1,%2,%3};"
        : "+f"(d[0]), "+f"(d[1]), "+f"(d[2]), "+f"(d[3])
        : "r"(a[0]), "r"(a[1]), "r"(a[2]), "r"(a[3]), "r"(b[0]), "r"(b[1]));
}

__global__ __launch_bounds__(128, 2) void gemm_tf32(
    const float* __restrict__ A, const float* __restrict__ W,
    const float* __restrict__ bias, float* __restrict__ C,
    int M, int N, int K, int relu)
{
    __shared__ float As[TBM * SSTR];   // [row][k] stride 20
    __shared__ float Bs[TBN * SSTR];   // [n][k]   stride 20

    int tid  = threadIdx.x;
    int warp = tid >> 5, lane = tid & 31;
    int wm = warp & 1, wn = warp >> 1;       // 2 x 2 warps
    int g = lane >> 2, c = lane & 3;

    int brow = blockIdx.y * TBM;
    int bcol = blockIdx.x * TBN;

    float acc[4][8][4];
    #pragma unroll
    for (int mt = 0; mt < 4; mt++)
        #pragma unroll
        for (int nt = 0; nt < 8; nt++)
            #pragma unroll
            for (int i = 0; i < 4; i++) acc[mt][nt][i] = 0.f;

    // staging mappings
    // A: thread owns row tid, 16 k-cols (4 float4)
    const float* aptr = A + (size_t)(brow + tid) * K;
    // B: thread owns k-row (tid&15), 16 n-cols starting (tid>>4)*16
    int bk = tid & 15, bn0 = (tid >> 4) * 16;
    const float* bptr = W + (size_t)bk * N + bcol + bn0;

    // prologue: fetch tile 0
    float4 ar0 = *(const float4*)(aptr + 0);
    float4 ar1 = *(const float4*)(aptr + 4);
    float4 ar2 = *(const float4*)(aptr + 8);
    float4 ar3 = *(const float4*)(aptr + 12);
    float4 br0 = *(const float4*)(bptr + 0);
    float4 br1 = *(const float4*)(bptr + 4);
    float4 br2 = *(const float4*)(bptr + 8);
    float4 br3 = *(const float4*)(bptr + 12);

    for (int k0 = 0; k0 < K; k0 += TBK) {
        // ---- stage to smem (round A to tf32 here) ----
        {
            float* arow = As + tid * SSTR;
            float4 t;
            t.x=tf32r(ar0.x); t.y=tf32r(ar0.y); t.z=tf32r(ar0.z); t.w=tf32r(ar0.w);
            *(float4*)(arow + 0) = t;
            t.x=tf32r(ar1.x); t.y=tf32r(ar1.y); t.z=tf32r(ar1.z); t.w=tf32r(ar1.w);
            *(float4*)(arow + 4) = t;
            t.x=tf32r(ar2.x); t.y=tf32r(ar2.y); t.z=tf32r(ar2.z); t.w=tf32r(ar2.w);
            *(float4*)(arow + 8) = t;
            t.x=tf32r(ar3.x); t.y=tf32r(ar3.y); t.z=tf32r(ar3.z); t.w=tf32r(ar3.w);
            *(float4*)(arow + 12) = t;
        }
        {
            // transpose-store B: Bs[n][k]
            Bs[(bn0 + 0)*SSTR + bk] = br0.x;  Bs[(bn0 + 1)*SSTR + bk] = br0.y;
            Bs[(bn0 + 2)*SSTR + bk] = br0.z;  Bs[(bn0 + 3)*SSTR + bk] = br0.w;
            Bs[(bn0 + 4)*SSTR + bk] = br1.x;  Bs[(bn0 + 5)*SSTR + bk] = br1.y;
            Bs[(bn0 + 6)*SSTR + bk] = br1.z;  Bs[(bn0 + 7)*SSTR + bk] = br1.w;
            Bs[(bn0 + 8)*SSTR + bk] = br2.x;  Bs[(bn0 + 9)*SSTR + bk] = br2.y;
            Bs[(bn0 +10)*SSTR + bk] = br2.z;  Bs[(bn0 +11)*SSTR + bk] = br2.w;
            Bs[(bn0 +12)*SSTR + bk] = br3.x;  Bs[(bn0 +13)*SSTR + bk] = br3.y;
            Bs[(bn0 +14)*SSTR + bk] = br3.z;  Bs[(bn0 +15)*SSTR + bk] = br3.w;
        }
        __syncthreads();

        // ---- prefetch next tile (hidden by mma chain) ----
        int kn = k0 + TBK;
        if (kn < K) {
            ar0 = *(const float4*)(aptr + kn + 0);
            ar1 = *(const float4*)(aptr + kn + 4);
            ar2 = *(const float4*)(aptr + kn + 8);
            ar3 = *(const float4*)(aptr + kn + 12);
            const float* bp = bptr + (size_t)kn * N;
            br0 = *(const float4*)(bp + 0);
            br1 = *(const float4*)(bp + 4);
            br2 = *(const float4*)(bp + 8);
            br3 = *(const float4*)(bp + 12);
        }

        // ---- compute ----
        #pragma unroll
        for (int ks = 0; ks < 2; ks++) {
            int kc = ks * 8 + c;
            unsigned bf[8][2];
            #pragma unroll
            for (int nt = 0; nt < 8; nt++) {
                int n = wn * 64 + nt * 8 + g;
                bf[nt][0] = __float_as_uint(Bs[n * SSTR + kc]);
                bf[nt][1] = __float_as_uint(Bs[n * SSTR + kc + 4]);
            }
            #pragma unroll
            for (int mt = 0; mt < 4; mt++) {
                int r0 = wm * 64 + mt * 16 + g;
                unsigned af[4];
                af[0] = __float_as_uint(As[r0 * SSTR + kc]);
                af[1] = __float_as_uint(As[(r0 + 8) * SSTR + kc]);
                af[2] = __float_as_uint(As[r0 * SSTR + kc + 4]);
                af[3] = __float_as_uint(As[(r0 + 8) * SSTR + kc + 4]);
                #pragma unroll
                for (int nt = 0; nt < 8; nt++)
                    mma1688(acc[mt][nt], af, bf[nt]);
            }
        }
        __syncthreads();
    }

    // ---- epilogue: bias (+relu) + store ----
    #pragma unroll
    for (int mt = 0; mt < 4; mt++) {
        int row = brow + wm * 64 + mt * 16 + g;
        #pragma unroll
        for (int nt = 0; nt < 8; nt++) {
            int col = bcol + wn * 64 + nt * 8 + 2 * c;
            float2 bs = *(const float2*)(bias + col);
            float v0 = acc[mt][nt][0] + bs.x;
            float v1 = acc[mt][nt][1] + bs.y;
            float v2 = acc[mt][nt][2] + bs.x;
            float v3 = acc[mt][nt][3] + bs.y;
            if (relu) {
                v0 = fmaxf(v0, 0.f); v1 = fmaxf(v1, 0.f);
                v2 = fmaxf(v2, 0.f); v3 = fmaxf(v3, 0.f);
            }
            *(float2*)(C + (size_t)row * N + col)       = make_float2(v0, v1);
            *(float2*)(C + (size_t)(row + 8) * N + col) = make_float2(v2, v3);
        }
    }
}

// =====================================================================
// Attention: block per (seq m, head h, 64-row q-tile), 256 threads.
// fp32 in / fp32 out (t1).
// =====================================================================
#define QT 64
#define KC 64
#define QSTR 129
#define KSTR 129
#define VSTR 132

__global__ __launch_bounds__(256) void attn2_kernel(
    const float* __restrict__ q, const float* __restrict__ k,
    const float* __restrict__ v, float* __restrict__ out,
    const int* __restrict__ lens, int Tt, int nQT)
{
    extern __shared__ float sm[];
    float* Qs  = sm;
    float* KVs = Qs + QT * QSTR;
    float* SC  = KVs + KC * VSTR;

    int tid = threadIdx.x;
    int b = blockIdx.x;
    int qt  = b % nQT; int rem = b / nQT;
    int h = rem % NHEAD; int m = rem / NHEAD;
    int q0 = qt * QT;
    int sstr = Tt + 1;

    int valid = Tt;
    if (lens) { int l = lens[m]; valid = l > 1 ? l : 1; }

    // ---- load Q tile ----
    const float* qbase = q + ((size_t)m * Tt + q0) * DMODEL + h * DHEAD;
    for (int i = tid; i < QT * (DHEAD/4); i += 256) {
        int row = i >> 5, c4 = i & 31;
        float4 vq = *(const float4*)(qbase + (size_t)row * DMODEL + 4 * c4);
        float* dst = Qs + row * QSTR + 4 * c4;
        dst[0] = vq.x; dst[1] = vq.y; dst[2] = vq.z; dst[3] = vq.w;
    }

    // ---- phase 1: raw scores ----
    int tq = (tid >> 4) << 2;
    int tk = (tid & 15) << 2;
    for (int kc = 0; kc < Tt; kc += KC) {
        __syncthreads();
        const float* kbase = k + ((size_t)m * Tt + kc) * DMODEL + h * DHEAD;
        for (int i = tid; i < KC * (DHEAD/4); i += 256) {
            int row = i >> 5, c4 = i & 31;
            float4 vk = *(const float4*)(kbase + (size_t)row * DMODEL + 4 * c4);
            float* dst = KVs + row * KSTR + 4 * c4;
            dst[0] = vk.x; dst[1] = vk.y; dst[2] = vk.z; dst[3] = vk.w;
        }
        __syncthreads();

        float acc[4][4];
        #pragma unroll
        for (int i = 0; i < 4; i++)
            #pragma unroll
            for (int j = 0; j < 4; j++) acc[i][j] = 0.f;

        const float* qp0 = Qs + (tq + 0) * QSTR;
        const float* qp1 = Qs + (tq + 1) * QSTR;
        const float* qp2 = Qs + (tq + 2) * QSTR;
        const float* qp3 = Qs + (tq + 3) * QSTR;
        const float* kp0 = KVs + (tk + 0) * KSTR;
        const float* kp1 = KVs + (tk + 1) * KSTR;
        const float* kp2 = KVs + (tk + 2) * KSTR;
        const float* kp3 = KVs + (tk + 3) * KSTR;

        #pragma unroll 4
        for (int d = 0; d < DHEAD; d++) {
            float qa[4] = { qp0[d], qp1[d], qp2[d], qp3[d] };
            float kb[4] = { kp0[d], kp1[d], kp2[d], kp3[d] };
            #pragma unroll
            for (int i = 0; i < 4; i++)
                #pragma unroll
                for (int j = 0; j < 4; j++)
                    acc[i][j] += qa[i] * kb[j];
        }
        #pragma unroll
        for (int i = 0; i < 4; i++)
            #pragma unroll
            for (int j = 0; j < 4; j++)
                SC[(tq + i) * sstr + kc + tk + j] = acc[i][j];
    }
    __syncthreads();

    // ---- phase 2: softmax per row ----
    {
        int warp = tid >> 5, lane = tid & 31;
        const float scale = 0.08838834764831845f;   // 1/sqrt(128)
        for (int rr = 0; rr < 8; rr++) {
            float* row = SC + (warp * 8 + rr) * sstr;
            float mx = -1e30f;
            for (int j = lane; j < Tt; j += 32) {
                float s = (j < valid) ? row[j] * scale : -1e9f;
                row[j] = s;
                mx = fmaxf(mx, s);
            }
            #pragma unroll
            for (int o = 16; o; o >>= 1) mx = fmaxf(mx, __shfl_xor_sync(0xffffffffu, mx, o));
            float sum = 0.f;
            for (int j = lane; j < Tt; j += 32) {
                float e = __expf(row[j] - mx);
                row[j] = e;
                sum += e;
            }
            #pragma unroll
            for (int o = 16; o; o >>= 1) sum += __shfl_xor_sync(0xffffffffu, sum, o);
            float inv = 1.f / sum;
            for (int j = lane; j < Tt; j += 32) row[j] *= inv;
        }
    }

    // ---- phase 3: P @ V ----
    int tqg = (tid >> 4) << 2;
    int td  = (tid & 15) << 3;
    float cacc[4][8];
    #pragma unroll
    for (int i = 0; i < 4; i++)
        #pragma unroll
        for (int j = 0; j < 8; j++) cacc[i][j] = 0.f;

    for (int kc = 0; kc < Tt; kc += KC) {
        __syncthreads();
        const float* vbase = v + ((size_t)m * Tt + kc) * DMODEL + h * DHEAD;
        for (int i = tid; i < KC * (DHEAD/4); i += 256) {
            int row = i >> 5, c4 = i & 31;
            float4 vv = *(const float4*)(vbase + (size_t)row * DMODEL + 4 * c4);
            *(float4*)(KVs + row * VSTR + 4 * c4) = vv;
        }
        __syncthreads();

        const float* pp0 = SC + (tqg + 0) * sstr + kc;
        const float* pp1 = SC + (tqg + 1) * sstr + kc;
        const float* pp2 = SC + (tqg + 2) * sstr + kc;
        const float* pp3 = SC + (tqg + 3) * sstr + kc;
        #pragma unroll 2
        for (int kk = 0; kk < KC; kk++) {
            float p[4] = { pp0[kk], pp1[kk], pp2[kk], pp3[kk] };
            float4 v0 = *(const float4*)(KVs + kk * VSTR + td);
            float4 v1 = *(const float4*)(KVs + kk * VSTR + td + 4);
            float vv[8] = { v0.x, v0.y, v0.z, v0.w, v1.x, v1.y, v1.z, v1.w };
            #pragma unroll
            for (int i = 0; i < 4; i++)
                #pragma unroll
                for (int j = 0; j < 8; j++)
                    cacc[i][j] += p[i] * vv[j];
        }
    }

    // ---- store ctx ----
    float* obase = out + ((size_t)m * Tt + q0) * DMODEL + h * DHEAD;
    #pragma unroll
    for (int i = 0; i < 4; i++) {
        float* orow = obase + (size_t)(tqg + i) * DMODEL + td;
        *(float4*)(orow)     = make_float4(cacc[i][0], cacc[i][1], cacc[i][2], cacc[i][3]);
        *(float4*)(orow + 4) = make_float4(cacc[i][4], cacc[i][5], cacc[i][6], cacc[i][7]);
    }
}

// ---------------- residual add + LayerNorm, block per token -----------------
__global__ void add_ln_kernel(const float* __restrict__ x, const float* __restrict__ y,
                              const float* __restrict__ g, const float* __restrict__ b,
                              float* __restrict__ out)
{
    int t = blockIdx.x, tid = threadIdx.x;
    const float* xr = x + (size_t)t * DMODEL;
    const float* yr = y + (size_t)t * DMODEL;
    int lane = tid & 31, warp = tid >> 5;
    __shared__ float red[4];

    float h[4];
    float s = 0.f;
    #pragma unroll
    for (int i = 0; i < 4; i++) { int d = tid + i * 128; h[i] = xr[d] + yr[d]; s += h[i]; }
    #pragma unroll
    for (int o = 16; o; o >>= 1) s += __shfl_xor_sync(0xffffffffu, s, o);
    if (lane == 0) red[warp] = s;
    __syncthreads();
    s = red[0] + red[1] + red[2] + red[3];
    float mu = s * (1.f / DMODEL);

    float vs = 0.f;
    #pragma unroll
    for (int i = 0; i < 4; i++) { float dl = h[i] - mu; vs += dl * dl; }
    #pragma unroll
    for (int o = 16; o; o >>= 1) vs += __shfl_xor_sync(0xffffffffu, vs, o);
    __syncthreads();
    if (lane == 0) red[warp] = vs;
    __syncthreads();
    vs = (red[0] + red[1] + red[2] + red[3]) * (1.f / DMODEL);
    float invstd = rsqrtf(vs + 1e-5f);

    float* orow = out + (size_t)t * DMODEL;
    #pragma unroll
    for (int i = 0; i < 4; i++) {
        int d = tid + i * 128;
        orow[d] = (h[i] - mu) * invstd * g[d] + b[d];
    }
}

// ---------------- embedding + positional encoding ---------------------------
__device__ __forceinline__ float pe_val(int pos, int d)
{
    int i2 = d & ~1;
    float div = expf((float)i2 * (-9.210340371976184f / (float)DMODEL));
    float ang = (float)pos * div;
    return (d & 1) ? cosf(ang) : sinf(ang);
}

__global__ void embed_kernel(const int* __restrict__ ids, const float* __restrict__ emb,
                             float* __restrict__ x, int seqlen)
{
    int tok = blockIdx.x;
    int pos = tok % seqlen;
    int id = ids[tok];
    const float* erow = emb + (size_t)id * DMODEL;
    float* xrow = x + (size_t)tok * DMODEL;
    for (int d = threadIdx.x; d < DMODEL; d += 128)
        xrow[d] = erow[d] + pe_val(pos, d);
}

// ---------------- small epilogue kernels -------------------------------------
__global__ void copy_hidden_kernel(const float* __restrict__ x, float* __restrict__ hid)
{
    int b = blockIdx.x;
    const float* src = x + ((size_t)(b * SLEN + SLEN - 1)) * DMODEL;
    for (int d = threadIdx.x; d < DMODEL; d += 128)
        hid[b * DMODEL + d] = src[d];
}

__global__ void gather_add_kernel(const float* __restrict__ hx, const int* __restrict__ lens,
                                  float* __restrict__ sep)
{
    int r = blockIdx.x;
    int len = lens[r];
    if (len <= 0) return;
    const float* src = hx + ((size_t)(r * TLEN + len - 1)) * DMODEL;
    for (int d = threadIdx.x; d < DMODEL; d += 128)
        sep[(size_t)r * DMODEL + d] += src[d];
}

__global__ void final_kernel(const float* __restrict__ sep, const float* __restrict__ hidden,
                             const int* __restrict__ normalize, float* __restrict__ out)
{
    int r = blockIdx.x;
    int b = r / NSEP;
    int tid = threadIdx.x;
    int lane = tid & 31, warp = tid >> 5;
    int norm = *normalize;

    __shared__ float sbuf[DMODEL];
    __shared__ float red[4];

    for (int d = tid; d < DMODEL; d += 128) {
        float v = sep[(size_t)r * DMODEL + d];
        if (norm) v = fmaxf(v, 0.f);
        sbuf[d] = v;
    }
    __syncthreads();

    float scale = 1.f;
    if (norm) {
        float ss = 0.f;
        for (int d = tid; d < DMODEL; d += 128) ss += sbuf[d] * sbuf[d];
        #pragma unroll
        for (int o = 16; o; o >>= 1) ss += __shfl_xor_sync(0xffffffffu, ss, o);
        if (lane == 0) red[warp] = ss;
        __syncthreads();
        ss = red[0] + red[1] + red[2] + red[3];
        float nrm = sqrtf(ss);
        scale = 1.f / fmaxf(nrm, 1e-12f);
        __syncthreads();
    }

    float dp = 0.f;
    for (int d = tid; d < DMODEL; d += 128)
        dp += sbuf[d] * scale * hidden[(size_t)b * DMODEL + d];
    #pragma unroll
    for (int o = 16; o; o >>= 1) dp += __shfl_xor_sync(0xffffffffu, dp, o);
    if (lane == 0) red[warp] = dp;
    __syncthreads();
    if (tid == 0) out[r] = red[0] + red[1] + red[2] + red[3];
}

// ---------------- host side ---------------------------------------------------
static void gemm(const float* A, const float* Wr, const float* bias, float* C,
                 int M, int N, int K, int relu)
{
    dim3 grid(N / TBN, M / TBM);
    gemm_tf32<<<grid, 128>>>(A, Wr, bias, C, M, N, K, relu);
}

struct EncParams {
    const float *wr;                    // base of rounded weight array
    const float *bq, *bk, *bv, *bo;
    const float *ln1g, *ln1b, *b1, *b2, *ln2g, *ln2b;
};

static void launch_attn(const float* q, const float* k, const float* v, float* out,
                        const int* lens, int M, int Tt)
{
    int nQT = Tt / QT;
    int grid = M * NHEAD * nQT;
    size_t smem = (size_t)(QT * QSTR + KC * VSTR + QT * (Tt + 1)) * sizeof(float);
    attn2_kernel<<<grid, 256, smem>>>(q, k, v, out, lens, Tt, nQT);
}

static void run_encoder(float* x, float* q, float* k, float* v, float* t1, float* t2,
                        const EncParams& p, const int* lens, int M, int Tt)
{
    int ntok = M * Tt;
    const int LW = DMODEL * DMODEL;
    for (int l = 0; l < NLAYER; l++) {
        const float* wq = p.wr + 0*WTSZ + (size_t)l * LW;
        const float* wk = p.wr + 1*WTSZ + (size_t)l * LW;
        const float* wv = p.wr + 2*WTSZ + (size_t)l * LW;
        const float* wo = p.wr + 3*WTSZ + (size_t)l * LW;
        const float* w1 = p.wr + 4*WTSZ + (size_t)l * LW;
        const float* w2 = p.wr + 5*WTSZ + (size_t)l * LW;

        gemm(x, wq, p.bq + l * DMODEL, q, ntok, DMODEL, DMODEL, 0);
        gemm(x, wk, p.bk + l * DMODEL, k, ntok, DMODEL, DMODEL, 0);
        gemm(x, wv, p.bv + l * DMODEL, v, ntok, DMODEL, DMODEL, 0);

        launch_attn(q, k, v, t1, lens, M, Tt);

        gemm(t1, wo, p.bo + l * DMODEL, t2, ntok, DMODEL, DMODEL, 0);
        add_ln_kernel<<<ntok, 128>>>(x, t2, p.ln1g + l * DMODEL, p.ln1b + l * DMODEL, x);

        gemm(x, w1, p.b1 + l * FFDIM, t1, ntok, FFDIM, DMODEL, 1);
        gemm(t1, w2, p.b2 + l * DMODEL, t2, ntok, DMODEL, FFDIM, 0);
        add_ln_kernel<<<ntok, 128>>>(x, t2, p.ln2g + l * DMODEL, p.ln2b + l * DMODEL, x);
    }
}

extern "C" void kernel_launch(void* const* d_in, const int* in_sizes, int n_in,
                              void* d_out, int out_size)
{
    const int*   segment    = (const int*)  d_in[0];
    const int*   prev_hist  = (const int*)  d_in[1];
    const int*   hist_len   = (const int*)  d_in[2];
    const float* sep_img    = (const float*)d_in[3];
    const int*   normalize  = (const int*)  d_in[4];
    const float* embedding  = (const float*)d_in[5];

    const float* Wq   = (const float*)d_in[6];  const float* bq   = (const float*)d_in[7];
    const float* Wk   = (const float*)d_in[8];  const float* bk   = (const float*)d_in[9];
    const float* Wv   = (const float*)d_in[10]; const float* bv   = (const float*)d_in[11];
    const float* Wo   = (const float*)d_in[12]; const float* bo   = (const float*)d_in[13];
    const float* ln1g = (const float*)d_in[14]; const float* ln1b = (const float*)d_in[15];
    const float* W1   = (const float*)d_in[16]; const float* b1   = (const float*)d_in[17];
    const float* W2   = (const float*)d_in[18]; const float* b2   = (const float*)d_in[19];
    const float* ln2g = (const float*)d_in[20]; const float* ln2b = (const float*)d_in[21];
    const float* Wsep = (const float*)d_in[22];
    const float* bsep = (const float*)d_in[23];

    float *x, *q, *k, *v, *t1, *t2, *hid, *sep, *wr;
    cudaGetSymbolAddress((void**)&x,   g_x);
    cudaGetSymbolAddress((void**)&q,   g_q);
    cudaGetSymbolAddress((void**)&k,   g_k);
    cudaGetSymbolAddress((void**)&v,   g_v);
    cudaGetSymbolAddress((void**)&t1,  g_t1);
    cudaGetSymbolAddress((void**)&t2,  g_t2);
    cudaGetSymbolAddress((void**)&hid, g_hidden);
    cudaGetSymbolAddress((void**)&sep, g_sep);
    cudaGetSymbolAddress((void**)&wr,  g_wr);

    cudaFuncSetAttribute(attn2_kernel, cudaFuncAttributeMaxDynamicSharedMemorySize, 140 * 1024);

    // ---- pre-round weights to tf32 ----
    {
        const float* srcs[7] = { Wq, Wk, Wv, Wo, W1, W2, Wsep };
        for (int t = 0; t < 7; t++) {
            int n4 = WTSZ / 4;
            wround_kernel<<<(n4 + 255) / 256, 256>>>(srcs[t], wr + (size_t)t * WTSZ, n4);
        }
    }

    EncParams p;
    p.wr = wr;
    p.bq = bq; p.bk = bk; p.bv = bv; p.bo = bo;
    p.ln1g = ln1g; p.ln1b = ln1b; p.b1 = b1; p.b2 = b2; p.ln2g = ln2g; p.ln2b = ln2b;

    // ---- main encoder ----
    embed_kernel<<<MAIN_TOK, 128>>>(segment, embedding, x, SLEN);
    run_encoder(x, q, k, v, t1, t2, p, nullptr, BATCH, SLEN);
    copy_hidden_kernel<<<BATCH, 128>>>(x, hid);

    // ---- separate image projection: (384,2048) @ (2048,512) + b ----
    gemm(sep_img, wr + (size_t)6 * WTSZ, bsep, sep, HIST_SEQ, FFDIM, IMGDIM, 0);

    // ---- history encoder ----
    embed_kernel<<<HIST_TOK, 128>>>(prev_hist, embedding, x, TLEN);
    run_encoder(x, q, k, v, t1, t2, p, hist_len, HIST_SEQ, TLEN);

    // ---- gather last hidden, add to sep, normalize + dot ----
    gather_add_kernel<<<HIST_SEQ, 128>>>(x, hist_len, sep);
    final_kernel<<<HIST_SEQ, 128>>>(sep, hid, normalize, (float*)d_out);
}

// round 8
// speedup vs baseline: 1.5015x; 1.0069x over previous
#include <cuda_runtime.h>
#include <math.h>

// Problem constants
#define BATCH 64
#define NSEP  6
#define SLEN  256
#define TLEN  64
#define DMODEL 512
#define NHEAD 4
#define DHEAD 128
#define FFDIM 512
#define NLAYER 4
#define IMGDIM 2048

#define MAIN_TOK (BATCH*SLEN)          // 16384
#define HIST_SEQ (BATCH*NSEP)          // 384
#define HIST_TOK (HIST_SEQ*TLEN)       // 24576
#define MAXTOK   HIST_TOK

// ---------------- scratch (device globals; no allocation allowed) ------------
__device__ float g_x [MAXTOK*DMODEL];
__device__ float g_q [MAXTOK*DMODEL];
__device__ float g_k [MAXTOK*DMODEL];
__device__ float g_v [MAXTOK*DMODEL];
__device__ float g_t1[MAXTOK*DMODEL];
__device__ float g_t2[MAXTOK*DMODEL];
__device__ float g_hidden[BATCH*DMODEL];
__device__ float g_sep[HIST_SEQ*DMODEL];

// Pre-rounded (tf32/rna) weights, stored as fp32 bit patterns:
// 0:Wq 1:Wk 2:Wv 3:Wo 4:W1 5:W2 6:Wsep   (all 1,048,576 elems)
#define WTSZ 1048576
__device__ float g_wr[7*WTSZ];

__device__ __forceinline__ float tf32r(float x)
{
    unsigned u;
    asm("cvt.rna.tf32.f32 %0, %1;" : "=r"(u) : "f"(x));
    return __uint_as_float(u);
}

// ---------------- one-time weight rounding -----------------------------------
__global__ void wround_kernel(const float* __restrict__ w, float* __restrict__ o, int n4)
{
    int i = blockIdx.x * 256 + threadIdx.x;
    if (i >= n4) return;
    float4 v = ((const float4*)w)[i];
    v.x = tf32r(v.x); v.y = tf32r(v.y); v.z = tf32r(v.z); v.w = tf32r(v.w);
    ((float4*)o)[i] = v;
}

// =====================================================================
// tf32 tensor-core GEMM: C = A[M,K] @ W[K,N] + bias, optional ReLU.
// W pre-rounded to tf32; A rounded (rna) at smem staging.
// Block tile 128x128x16, 256 threads (8 warps: 4 in M x 2 in N),
// warp tile 32x64. mma.m16n8k8.tf32.
// Requires: M%128==0, N%128==0, K%16==0 (all call sites satisfy).
// =====================================================================
#define TBM 128
#define TBN 128
#define TBK 16
#define SSTR 20    // float stride per row: 16 data + 4 pad

__device__ __forceinline__ void mma1688(float* d, const unsigned* a, const unsigned* b)
{
    asm volatile(
        "mma.sync.aligned.m16n8k8.row.col.f32.tf32.tf32.f32 "
        "{%0,%1,%2,%3},{%4,%5,%6,%7},{%8,%9},{%0,%1,%2,%3};"
        : "+f"(d[0]), "+f"(d[1]), "+f"(d[2]), "+f"(d[3])
        : "r"(a[0]), "r"(a[1]), "r"(a[2]), "r"(a[3]), "r"(b[0]), "r"(b[1]));
}

__global__ __launch_bounds__(256, 2) void gemm_tf32(
    const float* __restrict__ A, const float* __restrict__ W,
    const float* __restrict__ bias, float* __restrict__ C,
    int M, int N, int K, int relu)
{
    __shared__ float As[TBM * SSTR];   // [row][k] stride 20
    __shared__ float Bs[TBN * SSTR];   // [n][k]   stride 20

    int tid  = threadIdx.x;
    int warp = tid >> 5, lane = tid & 31;
    int wm = warp & 3, wn = warp >> 2;       // 4 x 2 warps
    int g = lane >> 2, c = lane & 3;

    int brow = blockIdx.y * TBM;
    int bcol = blockIdx.x * TBN;

    float acc[2][8][4];
    #pragma unroll
    for (int mt = 0; mt < 2; mt++)
        #pragma unroll
        for (int nt = 0; nt < 8; nt++)
            #pragma unroll
            for (int i = 0; i < 4; i++) acc[mt][nt][i] = 0.f;

    // staging mappings
    // A: thread pair per row: row = tid>>1, k-offset (tid&1)*8, 2 float4
    int a_row = tid >> 1, a_ko = (tid & 1) * 8;
    const float* aptr = A + (size_t)(brow + a_row) * K + a_ko;
    // B: thread owns k-row (tid&15), 8 n-cols starting (tid>>4)*8, 2 float4
    int bk = tid & 15, bn0 = (tid >> 4) * 8;
    const float* bptr = W + (size_t)bk * N + bcol + bn0;

    // prologue: fetch tile 0
    float4 ar0 = *(const float4*)(aptr + 0);
    float4 ar1 = *(const float4*)(aptr + 4);
    float4 br0 = *(const float4*)(bptr + 0);
    float4 br1 = *(const float4*)(bptr + 4);

    for (int k0 = 0; k0 < K; k0 += TBK) {
        // ---- stage to smem (round A to tf32 here) ----
        {
            float* arow = As + a_row * SSTR + a_ko;
            float4 t;
            t.x=tf32r(ar0.x); t.y=tf32r(ar0.y); t.z=tf32r(ar0.z); t.w=tf32r(ar0.w);
            *(float4*)(arow + 0) = t;
            t.x=tf32r(ar1.x); t.y=tf32r(ar1.y); t.z=tf32r(ar1.z); t.w=tf32r(ar1.w);
            *(float4*)(arow + 4) = t;
        }
        {
            // transpose-store B: Bs[n][k]
            Bs[(bn0 + 0)*SSTR + bk] = br0.x;  Bs[(bn0 + 1)*SSTR + bk] = br0.y;
            Bs[(bn0 + 2)*SSTR + bk] = br0.z;  Bs[(bn0 + 3)*SSTR + bk] = br0.w;
            Bs[(bn0 + 4)*SSTR + bk] = br1.x;  Bs[(bn0 + 5)*SSTR + bk] = br1.y;
            Bs[(bn0 + 6)*SSTR + bk] = br1.z;  Bs[(bn0 + 7)*SSTR + bk] = br1.w;
        }
        __syncthreads();

        // ---- prefetch next tile (hidden by mma chain) ----
        int kn = k0 + TBK;
        if (kn < K) {
            ar0 = *(const float4*)(aptr + kn + 0);
            ar1 = *(const float4*)(aptr + kn + 4);
            const float* bp = bptr + (size_t)kn * N;
            br0 = *(const float4*)(bp + 0);
            br1 = *(const float4*)(bp + 4);
        }

        // ---- compute ----
        #pragma unroll
        for (int ks = 0; ks < 2; ks++) {
            int kc = ks * 8 + c;
            unsigned bf[8][2];
            #pragma unroll
            for (int nt = 0; nt < 8; nt++) {
                int n = wn * 64 + nt * 8 + g;
                bf[nt][0] = __float_as_uint(Bs[n * SSTR + kc]);
                bf[nt][1] = __float_as_uint(Bs[n * SSTR + kc + 4]);
            }
            #pragma unroll
            for (int mt = 0; mt < 2; mt++) {
                int r0 = wm * 32 + mt * 16 + g;
                unsigned af[4];
                af[0] = __float_as_uint(As[r0 * SSTR + kc]);
                af[1] = __float_as_uint(As[(r0 + 8) * SSTR + kc]);
                af[2] = __float_as_uint(As[r0 * SSTR + kc + 4]);
                af[3] = __float_as_uint(As[(r0 + 8) * SSTR + kc + 4]);
                #pragma unroll
                for (int nt = 0; nt < 8; nt++)
                    mma1688(acc[mt][nt], af, bf[nt]);
            }
        }
        __syncthreads();
    }

    // ---- epilogue: bias (+relu) + store ----
    #pragma unroll
    for (int mt = 0; mt < 2; mt++) {
        int row = brow + wm * 32 + mt * 16 + g;
        #pragma unroll
        for (int nt = 0; nt < 8; nt++) {
            int col = bcol + wn * 64 + nt * 8 + 2 * c;
            float2 bs = *(const float2*)(bias + col);
            float v0 = acc[mt][nt][0] + bs.x;
            float v1 = acc[mt][nt][1] + bs.y;
            float v2 = acc[mt][nt][2] + bs.x;
            float v3 = acc[mt][nt][3] + bs.y;
            if (relu) {
                v0 = fmaxf(v0, 0.f); v1 = fmaxf(v1, 0.f);
                v2 = fmaxf(v2, 0.f); v3 = fmaxf(v3, 0.f);
            }
            *(float2*)(C + (size_t)row * N + col)       = make_float2(v0, v1);
            *(float2*)(C + (size_t)(row + 8) * N + col) = make_float2(v2, v3);
        }
    }
}

// =====================================================================
// Attention: block per (seq m, head h, 64-row q-tile), 256 threads.
// fp32 in / fp32 out (t1).
// =====================================================================
#define QT 64
#define KC 64
#define QSTR 129
#define KSTR 129
#define VSTR 132

__global__ __launch_bounds__(256) void attn2_kernel(
    const float* __restrict__ q, const float* __restrict__ k,
    const float* __restrict__ v, float* __restrict__ out,
    const int* __restrict__ lens, int Tt, int nQT)
{
    extern __shared__ float sm[];
    float* Qs  = sm;
    float* KVs = Qs + QT * QSTR;
    float* SC  = KVs + KC * VSTR;

    int tid = threadIdx.x;
    int b = blockIdx.x;
    int qt  = b % nQT; int rem = b / nQT;
    int h = rem % NHEAD; int m = rem / NHEAD;
    int q0 = qt * QT;
    int sstr = Tt + 1;

    int valid = Tt;
    if (lens) { int l = lens[m]; valid = l > 1 ? l : 1; }

    // ---- load Q tile ----
    const float* qbase = q + ((size_t)m * Tt + q0) * DMODEL + h * DHEAD;
    for (int i = tid; i < QT * (DHEAD/4); i += 256) {
        int row = i >> 5, c4 = i & 31;
        float4 vq = *(const float4*)(qbase + (size_t)row * DMODEL + 4 * c4);
        float* dst = Qs + row * QSTR + 4 * c4;
        dst[0] = vq.x; dst[1] = vq.y; dst[2] = vq.z; dst[3] = vq.w;
    }

    // ---- phase 1: raw scores ----
    int tq = (tid >> 4) << 2;
    int tk = (tid & 15) << 2;
    for (int kc = 0; kc < Tt; kc += KC) {
        __syncthreads();
        const float* kbase = k + ((size_t)m * Tt + kc) * DMODEL + h * DHEAD;
        for (int i = tid; i < KC * (DHEAD/4); i += 256) {
            int row = i >> 5, c4 = i & 31;
            float4 vk = *(const float4*)(kbase + (size_t)row * DMODEL + 4 * c4);
            float* dst = KVs + row * KSTR + 4 * c4;
            dst[0] = vk.x; dst[1] = vk.y; dst[2] = vk.z; dst[3] = vk.w;
        }
        __syncthreads();

        float acc[4][4];
        #pragma unroll
        for (int i = 0; i < 4; i++)
            #pragma unroll
            for (int j = 0; j < 4; j++) acc[i][j] = 0.f;

        const float* qp0 = Qs + (tq + 0) * QSTR;
        const float* qp1 = Qs + (tq + 1) * QSTR;
        const float* qp2 = Qs + (tq + 2) * QSTR;
        const float* qp3 = Qs + (tq + 3) * QSTR;
        const float* kp0 = KVs + (tk + 0) * KSTR;
        const float* kp1 = KVs + (tk + 1) * KSTR;
        const float* kp2 = KVs + (tk + 2) * KSTR;
        const float* kp3 = KVs + (tk + 3) * KSTR;

        #pragma unroll 4
        for (int d = 0; d < DHEAD; d++) {
            float qa[4] = { qp0[d], qp1[d], qp2[d], qp3[d] };
            float kb[4] = { kp0[d], kp1[d], kp2[d], kp3[d] };
            #pragma unroll
            for (int i = 0; i < 4; i++)
                #pragma unroll
                for (int j = 0; j < 4; j++)
                    acc[i][j] += qa[i] * kb[j];
        }
        #pragma unroll
        for (int i = 0; i < 4; i++)
            #pragma unroll
            for (int j = 0; j < 4; j++)
                SC[(tq + i) * sstr + kc + tk + j] = acc[i][j];
    }
    __syncthreads();

    // ---- phase 2: softmax per row ----
    {
        int warp = tid >> 5, lane = tid & 31;
        const float scale = 0.08838834764831845f;   // 1/sqrt(128)
        for (int rr = 0; rr < 8; rr++) {
            float* row = SC + (warp * 8 + rr) * sstr;
            float mx = -1e30f;
            for (int j = lane; j < Tt; j += 32) {
                float s = (j < valid) ? row[j] * scale : -1e9f;
                row[j] = s;
                mx = fmaxf(mx, s);
            }
            #pragma unroll
            for (int o = 16; o; o >>= 1) mx = fmaxf(mx, __shfl_xor_sync(0xffffffffu, mx, o));
            float sum = 0.f;
            for (int j = lane; j < Tt; j += 32) {
                float e = __expf(row[j] - mx);
                row[j] = e;
                sum += e;
            }
            #pragma unroll
            for (int o = 16; o; o >>= 1) sum += __shfl_xor_sync(0xffffffffu, sum, o);
            float inv = 1.f / sum;
            for (int j = lane; j < Tt; j += 32) row[j] *= inv;
        }
    }

    // ---- phase 3: P @ V ----
    int tqg = (tid >> 4) << 2;
    int td  = (tid & 15) << 3;
    float cacc[4][8];
    #pragma unroll
    for (int i = 0; i < 4; i++)
        #pragma unroll
        for (int j = 0; j < 8; j++) cacc[i][j] = 0.f;

    for (int kc = 0; kc < Tt; kc += KC) {
        __syncthreads();
        const float* vbase = v + ((size_t)m * Tt + kc) * DMODEL + h * DHEAD;
        for (int i = tid; i < KC * (DHEAD/4); i += 256) {
            int row = i >> 5, c4 = i & 31;
            float4 vv = *(const float4*)(vbase + (size_t)row * DMODEL + 4 * c4);
            *(float4*)(KVs + row * VSTR + 4 * c4) = vv;
        }
        __syncthreads();

        const float* pp0 = SC + (tqg + 0) * sstr + kc;
        const float* pp1 = SC + (tqg + 1) * sstr + kc;
        const float* pp2 = SC + (tqg + 2) * sstr + kc;
        const float* pp3 = SC + (tqg + 3) * sstr + kc;
        #pragma unroll 2
        for (int kk = 0; kk < KC; kk++) {
            float p[4] = { pp0[kk], pp1[kk], pp2[kk], pp3[kk] };
            float4 v0 = *(const float4*)(KVs + kk * VSTR + td);
            float4 v1 = *(const float4*)(KVs + kk * VSTR + td + 4);
            float vv[8] = { v0.x, v0.y, v0.z, v0.w, v1.x, v1.y, v1.z, v1.w };
            #pragma unroll
            for (int i = 0; i < 4; i++)
                #pragma unroll
                for (int j = 0; j < 8; j++)
                    cacc[i][j] += p[i] * vv[j];
        }
    }

    // ---- store ctx ----
    float* obase = out + ((size_t)m * Tt + q0) * DMODEL + h * DHEAD;
    #pragma unroll
    for (int i = 0; i < 4; i++) {
        float* orow = obase + (size_t)(tqg + i) * DMODEL + td;
        *(float4*)(orow)     = make_float4(cacc[i][0], cacc[i][1], cacc[i][2], cacc[i][3]);
        *(float4*)(orow + 4) = make_float4(cacc[i][4], cacc[i][5], cacc[i][6], cacc[i][7]);
    }
}

// ---------------- residual add + LayerNorm, block per token -----------------
__global__ void add_ln_kernel(const float* __restrict__ x, const float* __restrict__ y,
                              const float* __restrict__ g, const float* __restrict__ b,
                              float* __restrict__ out)
{
    int t = blockIdx.x, tid = threadIdx.x;
    const float* xr = x + (size_t)t * DMODEL;
    const float* yr = y + (size_t)t * DMODEL;
    int lane = tid & 31, warp = tid >> 5;
    __shared__ float red[4];

    float h[4];
    float s = 0.f;
    #pragma unroll
    for (int i = 0; i < 4; i++) { int d = tid + i * 128; h[i] = xr[d] + yr[d]; s += h[i]; }
    #pragma unroll
    for (int o = 16; o; o >>= 1) s += __shfl_xor_sync(0xffffffffu, s, o);
    if (lane == 0) red[warp] = s;
    __syncthreads();
    s = red[0] + red[1] + red[2] + red[3];
    float mu = s * (1.f / DMODEL);

    float vs = 0.f;
    #pragma unroll
    for (int i = 0; i < 4; i++) { float dl = h[i] - mu; vs += dl * dl; }
    #pragma unroll
    for (int o = 16; o; o >>= 1) vs += __shfl_xor_sync(0xffffffffu, vs, o);
    __syncthreads();
    if (lane == 0) red[warp] = vs;
    __syncthreads();
    vs = (red[0] + red[1] + red[2] + red[3]) * (1.f / DMODEL);
    float invstd = rsqrtf(vs + 1e-5f);

    float* orow = out + (size_t)t * DMODEL;
    #pragma unroll
    for (int i = 0; i < 4; i++) {
        int d = tid + i * 128;
        orow[d] = (h[i] - mu) * invstd * g[d] + b[d];
    }
}

// ---------------- embedding + positional encoding ---------------------------
__device__ __forceinline__ float pe_val(int pos, int d)
{
    int i2 = d & ~1;
    float div = expf((float)i2 * (-9.210340371976184f / (float)DMODEL));
    float ang = (float)pos * div;
    return (d & 1) ? cosf(ang) : sinf(ang);
}

__global__ void embed_kernel(const int* __restrict__ ids, const float* __restrict__ emb,
                             float* __restrict__ x, int seqlen)
{
    int tok = blockIdx.x;
    int pos = tok % seqlen;
    int id = ids[tok];
    const float* erow = emb + (size_t)id * DMODEL;
    float* xrow = x + (size_t)tok * DMODEL;
    for (int d = threadIdx.x; d < DMODEL; d += 128)
        xrow[d] = erow[d] + pe_val(pos, d);
}

// ---------------- small epilogue kernels -------------------------------------
__global__ void copy_hidden_kernel(const float* __restrict__ x, float* __restrict__ hid)
{
    int b = blockIdx.x;
    const float* src = x + ((size_t)(b * SLEN + SLEN - 1)) * DMODEL;
    for (int d = threadIdx.x; d < DMODEL; d += 128)
        hid[b * DMODEL + d] = src[d];
}

__global__ void gather_add_kernel(const float* __restrict__ hx, const int* __restrict__ lens,
                                  float* __restrict__ sep)
{
    int r = blockIdx.x;
    int len = lens[r];
    if (len <= 0) return;
    const float* src = hx + ((size_t)(r * TLEN + len - 1)) * DMODEL;
    for (int d = threadIdx.x; d < DMODEL; d += 128)
        sep[(size_t)r * DMODEL + d] += src[d];
}

__global__ void final_kernel(const float* __restrict__ sep, const float* __restrict__ hidden,
                             const int* __restrict__ normalize, float* __restrict__ out)
{
    int r = blockIdx.x;
    int b = r / NSEP;
    int tid = threadIdx.x;
    int lane = tid & 31, warp = tid >> 5;
    int norm = *normalize;

    __shared__ float sbuf[DMODEL];
    __shared__ float red[4];

    for (int d = tid; d < DMODEL; d += 128) {
        float v = sep[(size_t)r * DMODEL + d];
        if (norm) v = fmaxf(v, 0.f);
        sbuf[d] = v;
    }
    __syncthreads();

    float scale = 1.f;
    if (norm) {
        float ss = 0.f;
        for (int d = tid; d < DMODEL; d += 128) ss += sbuf[d] * sbuf[d];
        #pragma unroll
        for (int o = 16; o; o >>= 1) ss += __shfl_xor_sync(0xffffffffu, ss, o);
        if (lane == 0) red[warp] = ss;
        __syncthreads();
        ss = red[0] + red[1] + red[2] + red[3];
        float nrm = sqrtf(ss);
        scale = 1.f / fmaxf(nrm, 1e-12f);
        __syncthreads();
    }

    float dp = 0.f;
    for (int d = tid; d < DMODEL; d += 128)
        dp += sbuf[d] * scale * hidden[(size_t)b * DMODEL + d];
    #pragma unroll
    for (int o = 16; o; o >>= 1) dp += __shfl_xor_sync(0xffffffffu, dp, o);
    if (lane == 0) red[warp] = dp;
    __syncthreads();
    if (tid == 0) out[r] = red[0] + red[1] + red[2] + red[3];
}

// ---------------- host side ---------------------------------------------------
static void gemm(const float* A, const float* Wr, const float* bias, float* C,
                 int M, int N, int K, int relu)
{
    dim3 grid(N / TBN, M / TBM);
    gemm_tf32<<<grid, 256>>>(A, Wr, bias, C, M, N, K, relu);
}

struct EncParams {
    const float *wr;                    // base of rounded weight array
    const float *bq, *bk, *bv, *bo;
    const float *ln1g, *ln1b, *b1, *b2, *ln2g, *ln2b;
};

static void launch_attn(const float* q, const float* k, const float* v, float* out,
                        const int* lens, int M, int Tt)
{
    int nQT = Tt / QT;
    int grid = M * NHEAD * nQT;
    size_t smem = (size_t)(QT * QSTR + KC * VSTR + QT * (Tt + 1)) * sizeof(float);
    attn2_kernel<<<grid, 256, smem>>>(q, k, v, out, lens, Tt, nQT);
}

static void run_encoder(float* x, float* q, float* k, float* v, float* t1, float* t2,
                        const EncParams& p, const int* lens, int M, int Tt)
{
    int ntok = M * Tt;
    const int LW = DMODEL * DMODEL;
    for (int l = 0; l < NLAYER; l++) {
        const float* wq = p.wr + 0*WTSZ + (size_t)l * LW;
        const float* wk = p.wr + 1*WTSZ + (size_t)l * LW;
        const float* wv = p.wr + 2*WTSZ + (size_t)l * LW;
        const float* wo = p.wr + 3*WTSZ + (size_t)l * LW;
        const float* w1 = p.wr + 4*WTSZ + (size_t)l * LW;
        const float* w2 = p.wr + 5*WTSZ + (size_t)l * LW;

        gemm(x, wq, p.bq + l * DMODEL, q, ntok, DMODEL, DMODEL, 0);
        gemm(x, wk, p.bk + l * DMODEL, k, ntok, DMODEL, DMODEL, 0);
        gemm(x, wv, p.bv + l * DMODEL, v, ntok, DMODEL, DMODEL, 0);

        launch_attn(q, k, v, t1, lens, M, Tt);

        gemm(t1, wo, p.bo + l * DMODEL, t2, ntok, DMODEL, DMODEL, 0);
        add_ln_kernel<<<ntok, 128>>>(x, t2, p.ln1g + l * DMODEL, p.ln1b + l * DMODEL, x);

        gemm(x, w1, p.b1 + l * FFDIM, t1, ntok, FFDIM, DMODEL, 1);
        gemm(t1, w2, p.b2 + l * DMODEL, t2, ntok, DMODEL, FFDIM, 0);
        add_ln_kernel<<<ntok, 128>>>(x, t2, p.ln2g + l * DMODEL, p.ln2b + l * DMODEL, x);
    }
}

extern "C" void kernel_launch(void* const* d_in, const int* in_sizes, int n_in,
                              void* d_out, int out_size)
{
    const int*   segment    = (const int*)  d_in[0];
    const int*   prev_hist  = (const int*)  d_in[1];
    const int*   hist_len   = (const int*)  d_in[2];
    const float* sep_img    = (const float*)d_in[3];
    const int*   normalize  = (const int*)  d_in[4];
    const float* embedding  = (const float*)d_in[5];

    const float* Wq   = (const float*)d_in[6];  const float* bq   = (const float*)d_in[7];
    const float* Wk   = (const float*)d_in[8];  const float* bk   = (const float*)d_in[9];
    const float* Wv   = (const float*)d_in[10]; const float* bv   = (const float*)d_in[11];
    const float* Wo   = (const float*)d_in[12]; const float* bo   = (const float*)d_in[13];
    const float* ln1g = (const float*)d_in[14]; const float* ln1b = (const float*)d_in[15];
    const float* W1   = (const float*)d_in[16]; const float* b1   = (const float*)d_in[17];
    const float* W2   = (const float*)d_in[18]; const float* b2   = (const float*)d_in[19];
    const float* ln2g = (const float*)d_in[20]; const float* ln2b = (const float*)d_in[21];
    const float* Wsep = (const float*)d_in[22];
    const float* bsep = (const float*)d_in[23];

    float *x, *q, *k, *v, *t1, *t2, *hid, *sep, *wr;
    cudaGetSymbolAddress((void**)&x,   g_x);
    cudaGetSymbolAddress((void**)&q,   g_q);
    cudaGetSymbolAddress((void**)&k,   g_k);
    cudaGetSymbolAddress((void**)&v,   g_v);
    cudaGetSymbolAddress((void**)&t1,  g_t1);
    cudaGetSymbolAddress((void**)&t2,  g_t2);
    cudaGetSymbolAddress((void**)&hid, g_hidden);
    cudaGetSymbolAddress((void**)&sep, g_sep);
    cudaGetSymbolAddress((void**)&wr,  g_wr);

    cudaFuncSetAttribute(attn2_kernel, cudaFuncAttributeMaxDynamicSharedMemorySize, 140 * 1024);

    // ---- pre-round weights to tf32 ----
    {
        const float* srcs[7] = { Wq, Wk, Wv, Wo, W1, W2, Wsep };
        for (int t = 0; t < 7; t++) {
            int n4 = WTSZ / 4;
            wround_kernel<<<(n4 + 255) / 256, 256>>>(srcs[t], wr + (size_t)t * WTSZ, n4);
        }
    }

    EncParams p;
    p.wr = wr;
    p.bq = bq; p.bk = bk; p.bv = bv; p.bo = bo;
    p.ln1g = ln1g; p.ln1b = ln1b; p.b1 = b1; p.b2 = b2; p.ln2g = ln2g; p.ln2b = ln2b;

    // ---- main encoder ----
    embed_kernel<<<MAIN_TOK, 128>>>(segment, embedding, x, SLEN);
    run_encoder(x, q, k, v, t1, t2, p, nullptr, BATCH, SLEN);
    copy_hidden_kernel<<<BATCH, 128>>>(x, hid);

    // ---- separate image projection: (384,2048) @ (2048,512) + b ----
    gemm(sep_img, wr + (size_t)6 * WTSZ, bsep, sep, HIST_SEQ, FFDIM, IMGDIM, 0);

    // ---- history encoder ----
    embed_kernel<<<HIST_TOK, 128>>>(prev_hist, embedding, x, TLEN);
    run_encoder(x, q, k, v, t1, t2, p, hist_len, HIST_SEQ, TLEN);

    // ---- gather last hidden, add to sep, normalize + dot ----
    gather_add_kernel<<<HIST_SEQ, 128>>>(x, hist_len, sep);
    final_kernel<<<HIST_SEQ, 128>>>(sep, hid, normalize, (float*)d_out);
}

// round 10
// speedup vs baseline: 1.5288x; 1.0182x over previous
#include <cuda_runtime.h>
#include <math.h>

// Problem constants
#define BATCH 64
#define NSEP  6
#define SLEN  256
#define TLEN  64
#define DMODEL 512
#define NHEAD 4
#define DHEAD 128
#define FFDIM 512
#define NLAYER 4
#define IMGDIM 2048

#define MAIN_TOK (BATCH*SLEN)          // 16384
#define HIST_SEQ (BATCH*NSEP)          // 384
#define HIST_TOK (HIST_SEQ*TLEN)       // 24576
#define MAXTOK   HIST_TOK

// ---------------- scratch (device globals; no allocation allowed) ------------
__device__ float g_x [MAXTOK*DMODEL];
__device__ float g_q [MAXTOK*DMODEL];
__device__ float g_k [MAXTOK*DMODEL];
__device__ float g_v [MAXTOK*DMODEL];
__device__ float g_t1[MAXTOK*DMODEL];
__device__ float g_t2[MAXTOK*DMODEL];
__device__ float g_hidden[BATCH*DMODEL];
__device__ float g_sep[HIST_SEQ*DMODEL];

// Pre-rounded (tf32/rna) weights: 0:Wq 1:Wk 2:Wv 3:Wo 4:W1 5:W2 6:Wsep
#define WTSZ 1048576
__device__ float g_wr[7*WTSZ];

__device__ __forceinline__ float tf32r(float x)
{
    unsigned u;
    asm("cvt.rna.tf32.f32 %0, %1;" : "=r"(u) : "f"(x));
    return __uint_as_float(u);
}

// ---------------- one-time weight rounding (single launch, grid.y = tensor) --
__global__ void wround_all(const float* w0, const float* w1, const float* w2,
                           const float* w3, const float* w4, const float* w5,
                           const float* w6, float* out, int n4)
{
    const float* srcs[7] = { w0, w1, w2, w3, w4, w5, w6 };
    int t = blockIdx.y;
    const float* w = srcs[t];
    float* o = out + (size_t)t * WTSZ;
    int i = blockIdx.x * 256 + threadIdx.x;
    if (i >= n4) return;
    float4 v = ((const float4*)w)[i];
    v.x = tf32r(v.x); v.y = tf32r(v.y); v.z = tf32r(v.z); v.w = tf32r(v.w);
    ((float4*)o)[i] = v;
}

// =====================================================================
// tf32 tensor-core GEMM: C = A[M,K] @ W[K,N] + bias, optional ReLU.
// W pre-rounded; A staged raw via cp.async (HW truncates fp32->tf32).
// Block 128x128x16, 256 threads (8 warps 4x2), warp tile 32x64.
// 3-stage cp.async pipeline on the A stream; B via register prefetch
// + transpose store (conflict-free fragment loads).
// Requires: M%128==0, N%128==0, K%16==0.
// =====================================================================
#define TBM 128
#define TBN 128
#define TBK 16
#define SSTR 20    // float stride: 16 data + 4 pad (16B-aligned rows)
#define NSTAGE 3

__device__ __forceinline__ void mma1688(float* d, const unsigned* a, const unsigned* b)
{
    asm volatile(
        "mma.sync.aligned.m16n8k8.row.col.f32.tf32.tf32.f32 "
        "{%0,%1,%2,%3},{%4,%5,%6,%7},{%8,%9},{%0,%1,%2,%3};"
        : "+f"(d[0]), "+f"(d[1]), "+f"(d[2]), "+f"(d[3])
        : "r"(a[0]), "r"(a[1]), "r"(a[2]), "r"(a[3]), "r"(b[0]), "r"(b[1]));
}

__device__ __forceinline__ void cpa16(unsigned s, const void* g)
{
    asm volatile("cp.async.ca.shared.global [%0], [%1], 16;" :: "r"(s), "l"(g));
}

__global__ __launch_bounds__(256, 2) void gemm_tf32(
    const float* __restrict__ A, const float* __restrict__ W,
    const float* __restrict__ bias, float* __restrict__ C,
    int M, int N, int K, int relu)
{
    __shared__ float As[NSTAGE][TBM * SSTR];   // [row][k]
    __shared__ float Bs[TBN * SSTR];           // [n][k]

    int tid  = threadIdx.x;
    int warp = tid >> 5, lane = tid & 31;
    int wm = warp & 3, wn = warp >> 2;         // 4 x 2 warps
    int g = lane >> 2, c = lane & 3;

    int brow = blockIdx.y * TBM;
    int bcol = blockIdx.x * TBN;

    float acc[2][8][4];
    #pragma unroll
    for (int mt = 0; mt < 2; mt++)
        #pragma unroll
        for (int nt = 0; nt < 8; nt++)
            #pragma unroll
            for (int i = 0; i < 4; i++) acc[mt][nt][i] = 0.f;

    // A staging: row = tid>>1, k-offset (tid&1)*8, two 16B cp.async per stage
    int a_row = tid >> 1, a_ko = (tid & 1) * 8;
    const float* aptr = A + (size_t)(brow + a_row) * K + a_ko;
    unsigned sbaseA[NSTAGE];
    #pragma unroll
    for (int s = 0; s < NSTAGE; s++)
        sbaseA[s] = (unsigned)__cvta_generic_to_shared(&As[s][a_row * SSTR + a_ko]);

    // B staging: k-row (tid&15), 8 n-cols at (tid>>4)*8, 2 float4 regs
    int bk = tid & 15, bn0 = (tid >> 4) * 8;
    const float* bptr = W + (size_t)bk * N + bcol + bn0;

    int niter = K / TBK;

    // ---- prologue: A stages 0,1 + B regs for tile 0 ----
    cpa16(sbaseA[0], aptr);
    cpa16(sbaseA[0] + 16, aptr + 4);
    asm volatile("cp.async.commit_group;");
    cpa16(sbaseA[1], aptr + TBK);
    cpa16(sbaseA[1] + 16, aptr + TBK + 4);
    asm volatile("cp.async.commit_group;");

    float4 br0 = *(const float4*)(bptr + 0);
    float4 br1 = *(const float4*)(bptr + 4);

    int st = 0;
    for (int i = 0; i < niter; i++) {
        // ---- store B regs (transpose) ----
        Bs[(bn0 + 0)*SSTR + bk] = br0.x;  Bs[(bn0 + 1)*SSTR + bk] = br0.y;
        Bs[(bn0 + 2)*SSTR + bk] = br0.z;  Bs[(bn0 + 3)*SSTR + bk] = br0.w;
        Bs[(bn0 + 4)*SSTR + bk] = br1.x;  Bs[(bn0 + 5)*SSTR + bk] = br1.y;
        Bs[(bn0 + 6)*SSTR + bk] = br1.z;  Bs[(bn0 + 7)*SSTR + bk] = br1.w;

        asm volatile("cp.async.wait_group 1;");
        __syncthreads();

        // ---- issue A stage i+2, always commit (empty group if past end) ----
        int kt = i + 2;
        if (kt < niter) {
            const float* ga = aptr + (size_t)kt * TBK;
            int sn = kt - NSTAGE * (kt / NSTAGE);     // kt % 3
            unsigned sa = sbaseA[sn];
            cpa16(sa, ga);
            cpa16(sa + 16, ga + 4);
        }
        asm volatile("cp.async.commit_group;");

        // ---- B regs for next tile ----
        if (i + 1 < niter) {
            const float* bp = bptr + (size_t)(i + 1) * TBK * N;
            br0 = *(const float4*)(bp + 0);
            br1 = *(const float4*)(bp + 4);
        }

        // ---- compute from As[st], Bs ----
        const float* ASP = As[st];
        #pragma unroll
        for (int ks = 0; ks < 2; ks++) {
            int kc = ks * 8 + c;
            unsigned bf[8][2];
            #pragma unroll
            for (int nt = 0; nt < 8; nt++) {
                int n = wn * 64 + nt * 8 + g;
                bf[nt][0] = __float_as_uint(Bs[n * SSTR + kc]);
                bf[nt][1] = __float_as_uint(Bs[n * SSTR + kc + 4]);
            }
            #pragma unroll
            for (int mt = 0; mt < 2; mt++) {
                int r0 = wm * 32 + mt * 16 + g;
                unsigned af[4];
                af[0] = __float_as_uint(ASP[r0 * SSTR + kc]);
                af[1] = __float_as_uint(ASP[(r0 + 8) * SSTR + kc]);
                af[2] = __float_as_uint(ASP[r0 * SSTR + kc + 4]);
                af[3] = __float_as_uint(ASP[(r0 + 8) * SSTR + kc + 4]);
                #pragma unroll
                for (int nt = 0; nt < 8; nt++)
                    mma1688(acc[mt][nt], af, bf[nt]);
            }
        }
        __syncthreads();

        st++;
        if (st == NSTAGE) st = 0;
    }

    // ---- epilogue: bias (+relu) + store ----
    #pragma unroll
    for (int mt = 0; mt < 2; mt++) {
        int row = brow + wm * 32 + mt * 16 + g;
        #pragma unroll
        for (int nt = 0; nt < 8; nt++) {
            int col = bcol + wn * 64 + nt * 8 + 2 * c;
            float2 bs = *(const float2*)(bias + col);
            float v0 = acc[mt][nt][0] + bs.x;
            float v1 = acc[mt][nt][1] + bs.y;
            float v2 = acc[mt][nt][2] + bs.x;
            float v3 = acc[mt][nt][3] + bs.y;
            if (relu) {
                v0 = fmaxf(v0, 0.f); v1 = fmaxf(v1, 0.f);
                v2 = fmaxf(v2, 0.f); v3 = fmaxf(v3, 0.f);
            }
            *(float2*)(C + (size_t)row * N + col)       = make_float2(v0, v1);
            *(float2*)(C + (size_t)(row + 8) * N + col) = make_float2(v2, v3);
        }
    }
}

// =====================================================================
// Attention: block per (seq m, head h, 64-row q-tile), 256 threads.
// =====================================================================
#define QT 64
#define KC 64
#define QSTR 129
#define KSTR 129
#define VSTR 132

__global__ __launch_bounds__(256) void attn2_kernel(
    const float* __restrict__ q, const float* __restrict__ k,
    const float* __restrict__ v, float* __restrict__ out,
    const int* __restrict__ lens, int Tt, int nQT)
{
    extern __shared__ float sm[];
    float* Qs  = sm;
    float* KVs = Qs + QT * QSTR;
    float* SC  = KVs + KC * VSTR;

    int tid = threadIdx.x;
    int b = blockIdx.x;
    int qt  = b % nQT; int rem = b / nQT;
    int h = rem % NHEAD; int m = rem / NHEAD;
    int q0 = qt * QT;
    int sstr = Tt + 1;

    int valid = Tt;
    if (lens) { int l = lens[m]; valid = l > 1 ? l : 1; }

    // ---- load Q tile ----
    const float* qbase = q + ((size_t)m * Tt + q0) * DMODEL + h * DHEAD;
    for (int i = tid; i < QT * (DHEAD/4); i += 256) {
        int row = i >> 5, c4 = i & 31;
        float4 vq = *(const float4*)(qbase + (size_t)row * DMODEL + 4 * c4);
        float* dst = Qs + row * QSTR + 4 * c4;
        dst[0] = vq.x; dst[1] = vq.y; dst[2] = vq.z; dst[3] = vq.w;
    }

    // ---- phase 1: raw scores ----
    int tq = (tid >> 4) << 2;
    int tk = (tid & 15) << 2;
    for (int kc = 0; kc < Tt; kc += KC) {
        __syncthreads();
        const float* kbase = k + ((size_t)m * Tt + kc) * DMODEL + h * DHEAD;
        for (int i = tid; i < KC * (DHEAD/4); i += 256) {
            int row = i >> 5, c4 = i & 31;
            float4 vk = *(const float4*)(kbase + (size_t)row * DMODEL + 4 * c4);
            float* dst = KVs + row * KSTR + 4 * c4;
            dst[0] = vk.x; dst[1] = vk.y; dst[2] = vk.z; dst[3] = vk.w;
        }
        __syncthreads();

        float acc[4][4];
        #pragma unroll
        for (int i = 0; i < 4; i++)
            #pragma unroll
            for (int j = 0; j < 4; j++) acc[i][j] = 0.f;

        const float* qp0 = Qs + (tq + 0) * QSTR;
        const float* qp1 = Qs + (tq + 1) * QSTR;
        const float* qp2 = Qs + (tq + 2) * QSTR;
        const float* qp3 = Qs + (tq + 3) * QSTR;
        const float* kp0 = KVs + (tk + 0) * KSTR;
        const float* kp1 = KVs + (tk + 1) * KSTR;
        const float* kp2 = KVs + (tk + 2) * KSTR;
        const float* kp3 = KVs + (tk + 3) * KSTR;

        #pragma unroll 4
        for (int d = 0; d < DHEAD; d++) {
            float qa[4] = { qp0[d], qp1[d], qp2[d], qp3[d] };
            float kb[4] = { kp0[d], kp1[d], kp2[d], kp3[d] };
            #pragma unroll
            for (int i = 0; i < 4; i++)
                #pragma unroll
                for (int j = 0; j < 4; j++)
                    acc[i][j] += qa[i] * kb[j];
        }
        #pragma unroll
        for (int i = 0; i < 4; i++)
            #pragma unroll
            for (int j = 0; j < 4; j++)
                SC[(tq + i) * sstr + kc + tk + j] = acc[i][j];
    }
    __syncthreads();

    // ---- phase 2: softmax per row ----
    {
        int warp = tid >> 5, lane = tid & 31;
        const float scale = 0.08838834764831845f;   // 1/sqrt(128)
        for (int rr = 0; rr < 8; rr++) {
            float* row = SC + (warp * 8 + rr) * sstr;
            float mx = -1e30f;
            for (int j = lane; j < Tt; j += 32) {
                float s = (j < valid) ? row[j] * scale : -1e9f;
                row[j] = s;
                mx = fmaxf(mx, s);
            }
            #pragma unroll
            for (int o = 16; o; o >>= 1) mx = fmaxf(mx, __shfl_xor_sync(0xffffffffu, mx, o));
            float sum = 0.f;
            for (int j = lane; j < Tt; j += 32) {
                float e = __expf(row[j] - mx);
                row[j] = e;
                sum += e;
            }
            #pragma unroll
            for (int o = 16; o; o >>= 1) sum += __shfl_xor_sync(0xffffffffu, sum, o);
            float inv = 1.f / sum;
            for (int j = lane; j < Tt; j += 32) row[j] *= inv;
        }
    }

    // ---- phase 3: P @ V ----
    int tqg = (tid >> 4) << 2;
    int td  = (tid & 15) << 3;
    float cacc[4][8];
    #pragma unroll
    for (int i = 0; i < 4; i++)
        #pragma unroll
        for (int j = 0; j < 8; j++) cacc[i][j] = 0.f;

    for (int kc = 0; kc < Tt; kc += KC) {
        __syncthreads();
        const float* vbase = v + ((size_t)m * Tt + kc) * DMODEL + h * DHEAD;
        for (int i = tid; i < KC * (DHEAD/4); i += 256) {
            int row = i >> 5, c4 = i & 31;
            float4 vv = *(const float4*)(vbase + (size_t)row * DMODEL + 4 * c4);
            *(float4*)(KVs + row * VSTR + 4 * c4) = vv;
        }
        __syncthreads();

        const float* pp0 = SC + (tqg + 0) * sstr + kc;
        const float* pp1 = SC + (tqg + 1) * sstr + kc;
        const float* pp2 = SC + (tqg + 2) * sstr + kc;
        const float* pp3 = SC + (tqg + 3) * sstr + kc;
        #pragma unroll 2
        for (int kk = 0; kk < KC; kk++) {
            float p[4] = { pp0[kk], pp1[kk], pp2[kk], pp3[kk] };
            float4 v0 = *(const float4*)(KVs + kk * VSTR + td);
            float4 v1 = *(const float4*)(KVs + kk * VSTR + td + 4);
            float vv[8] = { v0.x, v0.y, v0.z, v0.w, v1.x, v1.y, v1.z, v1.w };
            #pragma unroll
            for (int i = 0; i < 4; i++)
                #pragma unroll
                for (int j = 0; j < 8; j++)
                    cacc[i][j] += p[i] * vv[j];
        }
    }

    // ---- store ctx ----
    float* obase = out + ((size_t)m * Tt + q0) * DMODEL + h * DHEAD;
    #pragma unroll
    for (int i = 0; i < 4; i++) {
        float* orow = obase + (size_t)(tqg + i) * DMODEL + td;
        *(float4*)(orow)     = make_float4(cacc[i][0], cacc[i][1], cacc[i][2], cacc[i][3]);
        *(float4*)(orow + 4) = make_float4(cacc[i][4], cacc[i][5], cacc[i][6], cacc[i][7]);
    }
}

// ---------------- residual add + LayerNorm, block per token -----------------
__global__ void add_ln_kernel(const float* __restrict__ x, const float* __restrict__ y,
                              const float* __restrict__ g, const float* __restrict__ b,
                              float* __restrict__ out)
{
    int t = blockIdx.x, tid = threadIdx.x;
    const float* xr = x + (size_t)t * DMODEL;
    const float* yr = y + (size_t)t * DMODEL;
    int lane = tid & 31, warp = tid >> 5;
    __shared__ float red[4];

    float h[4];
    float s = 0.f;
    #pragma unroll
    for (int i = 0; i < 4; i++) { int d = tid + i * 128; h[i] = xr[d] + yr[d]; s += h[i]; }
    #pragma unroll
    for (int o = 16; o; o >>= 1) s += __shfl_xor_sync(0xffffffffu, s, o);
    if (lane == 0) red[warp] = s;
    __syncthreads();
    s = red[0] + red[1] + red[2] + red[3];
    float mu = s * (1.f / DMODEL);

    float vs = 0.f;
    #pragma unroll
    for (int i = 0; i < 4; i++) { float dl = h[i] - mu; vs += dl * dl; }
    #pragma unroll
    for (int o = 16; o; o >>= 1) vs += __shfl_xor_sync(0xffffffffu, vs, o);
    __syncthreads();
    if (lane == 0) red[warp] = vs;
    __syncthreads();
    vs = (red[0] + red[1] + red[2] + red[3]) * (1.f / DMODEL);
    float invstd = rsqrtf(vs + 1e-5f);

    float* orow = out + (size_t)t * DMODEL;
    #pragma unroll
    for (int i = 0; i < 4; i++) {
        int d = tid + i * 128;
        orow[d] = (h[i] - mu) * invstd * g[d] + b[d];
    }
}

// ---------------- embedding + positional encoding ---------------------------
__device__ __forceinline__ float pe_val(int pos, int d)
{
    int i2 = d & ~1;
    float div = expf((float)i2 * (-9.210340371976184f / (float)DMODEL));
    float ang = (float)pos * div;
    return (d & 1) ? cosf(ang) : sinf(ang);
}

__global__ void embed_kernel(const int* __restrict__ ids, const float* __restrict__ emb,
                             float* __restrict__ x, int seqlen)
{
    int tok = blockIdx.x;
    int pos = tok % seqlen;
    int id = ids[tok];
    const float* erow = emb + (size_t)id * DMODEL;
    float* xrow = x + (size_t)tok * DMODEL;
    for (int d = threadIdx.x; d < DMODEL; d += 128)
        xrow[d] = erow[d] + pe_val(pos, d);
}

// ---------------- small epilogue kernels -------------------------------------
__global__ void copy_hidden_kernel(const float* __restrict__ x, float* __restrict__ hid)
{
    int b = blockIdx.x;
    const float* src = x + ((size_t)(b * SLEN + SLEN - 1)) * DMODEL;
    for (int d = threadIdx.x; d < DMODEL; d += 128)
        hid[b * DMODEL + d] = src[d];
}

__global__ void gather_add_kernel(const float* __restrict__ hx, const int* __restrict__ lens,
                                  float* __restrict__ sep)
{
    int r = blockIdx.x;
    int len = lens[r];
    if (len <= 0) return;
    const float* src = hx + ((size_t)(r * TLEN + len - 1)) * DMODEL;
    for (int d = threadIdx.x; d < DMODEL; d += 128)
        sep[(size_t)r * DMODEL + d] += src[d];
}

__global__ void final_kernel(const float* __restrict__ sep, const float* __restrict__ hidden,
                             const int* __restrict__ normalize, float* __restrict__ out)
{
    int r = blockIdx.x;
    int b = r / NSEP;
    int tid = threadIdx.x;
    int lane = tid & 31, warp = tid >> 5;
    int norm = *normalize;

    __shared__ float sbuf[DMODEL];
    __shared__ float red[4];

    for (int d = tid; d < DMODEL; d += 128) {
        float v = sep[(size_t)r * DMODEL + d];
        if (norm) v = fmaxf(v, 0.f);
        sbuf[d] = v;
    }
    __syncthreads();

    float scale = 1.f;
    if (norm) {
        float ss = 0.f;
        for (int d = tid; d < DMODEL; d += 128) ss += sbuf[d] * sbuf[d];
        #pragma unroll
        for (int o = 16; o; o >>= 1) ss += __shfl_xor_sync(0xffffffffu, ss, o);
        if (lane == 0) red[warp] = ss;
        __syncthreads();
        ss = red[0] + red[1] + red[2] + red[3];
        float nrm = sqrtf(ss);
        scale = 1.f / fmaxf(nrm, 1e-12f);
        __syncthreads();
    }

    float dp = 0.f;
    for (int d = tid; d < DMODEL; d += 128)
        dp += sbuf[d] * scale * hidden[(size_t)b * DMODEL + d];
    #pragma unroll
    for (int o = 16; o; o >>= 1) dp += __shfl_xor_sync(0xffffffffu, dp, o);
    if (lane == 0) red[warp] = dp;
    __syncthreads();
    if (tid == 0) out[r] = red[0] + red[1] + red[2] + red[3];
}

// ---------------- host side ---------------------------------------------------
static void gemm(const float* A, const float* Wr, const float* bias, float* C,
                 int M, int N, int K, int relu)
{
    dim3 grid(N / TBN, M / TBM);
    gemm_tf32<<<grid, 256>>>(A, Wr, bias, C, M, N, K, relu);
}

struct EncParams {
    const float *wr;
    const float *bq, *bk, *bv, *bo;
    const float *ln1g, *ln1b, *b1, *b2, *ln2g, *ln2b;
};

static void launch_attn(const float* q, const float* k, const float* v, float* out,
                        const int* lens, int M, int Tt)
{
    int nQT = Tt / QT;
    int grid = M * NHEAD * nQT;
    size_t smem = (size_t)(QT * QSTR + KC * VSTR + QT * (Tt + 1)) * sizeof(float);
    attn2_kernel<<<grid, 256, smem>>>(q, k, v, out, lens, Tt, nQT);
}

static void run_encoder(float* x, float* q, float* k, float* v, float* t1, float* t2,
                        const EncParams& p, const int* lens, int M, int Tt)
{
    int ntok = M * Tt;
    const int LW = DMODEL * DMODEL;
    for (int l = 0; l < NLAYER; l++) {
        const float* wq = p.wr + 0*WTSZ + (size_t)l * LW;
        const float* wk = p.wr + 1*WTSZ + (size_t)l * LW;
        const float* wv = p.wr + 2*WTSZ + (size_t)l * LW;
        const float* wo = p.wr + 3*WTSZ + (size_t)l * LW;
        const float* w1 = p.wr + 4*WTSZ + (size_t)l * LW;
        const float* w2 = p.wr + 5*WTSZ + (size_t)l * LW;

        gemm(x, wq, p.bq + l * DMODEL, q, ntok, DMODEL, DMODEL, 0);
        gemm(x, wk, p.bk + l * DMODEL, k, ntok, DMODEL, DMODEL, 0);
        gemm(x, wv, p.bv + l * DMODEL, v, ntok, DMODEL, DMODEL, 0);

        launch_attn(q, k, v, t1, lens, M, Tt);

        gemm(t1, wo, p.bo + l * DMODEL, t2, ntok, DMODEL, DMODEL, 0);
        add_ln_kernel<<<ntok, 128>>>(x, t2, p.ln1g + l * DMODEL, p.ln1b + l * DMODEL, x);

        gemm(x, w1, p.b1 + l * FFDIM, t1, ntok, FFDIM, DMODEL, 1);
        gemm(t1, w2, p.b2 + l * DMODEL, t2, ntok, DMODEL, FFDIM, 0);
        add_ln_kernel<<<ntok, 128>>>(x, t2, p.ln2g + l * DMODEL, p.ln2b + l * DMODEL, x);
    }
}

extern "C" void kernel_launch(void* const* d_in, const int* in_sizes, int n_in,
                              void* d_out, int out_size)
{
    const int*   segment    = (const int*)  d_in[0];
    const int*   prev_hist  = (const int*)  d_in[1];
    const int*   hist_len   = (const int*)  d_in[2];
    const float* sep_img    = (const float*)d_in[3];
    const int*   normalize  = (const int*)  d_in[4];
    const float* embedding  = (const float*)d_in[5];

    const float* Wq   = (const float*)d_in[6];  const float* bq   = (const float*)d_in[7];
    const float* Wk   = (const float*)d_in[8];  const float* bk   = (const float*)d_in[9];
    const float* Wv   = (const float*)d_in[10]; const float* bv   = (const float*)d_in[11];
    const float* Wo   = (const float*)d_in[12]; const float* bo   = (const float*)d_in[13];
    const float* ln1g = (const float*)d_in[14]; const float* ln1b = (const float*)d_in[15];
    const float* W1   = (const float*)d_in[16]; const float* b1   = (const float*)d_in[17];
    const float* W2   = (const float*)d_in[18]; const float* b2   = (const float*)d_in[19];
    const float* ln2g = (const float*)d_in[20]; const float* ln2b = (const float*)d_in[21];
    const float* Wsep = (const float*)d_in[22];
    const float* bsep = (const float*)d_in[23];

    float *x, *q, *k, *v, *t1, *t2, *hid, *sep, *wr;
    cudaGetSymbolAddress((void**)&x,   g_x);
    cudaGetSymbolAddress((void**)&q,   g_q);
    cudaGetSymbolAddress((void**)&k,   g_k);
    cudaGetSymbolAddress((void**)&v,   g_v);
    cudaGetSymbolAddress((void**)&t1,  g_t1);
    cudaGetSymbolAddress((void**)&t2,  g_t2);
    cudaGetSymbolAddress((void**)&hid, g_hidden);
    cudaGetSymbolAddress((void**)&sep, g_sep);
    cudaGetSymbolAddress((void**)&wr,  g_wr);

    cudaFuncSetAttribute(attn2_kernel, cudaFuncAttributeMaxDynamicSharedMemorySize, 140 * 1024);

    // ---- launch 1: round all weights to tf32 (single launch) ----
    {
        dim3 grid(WTSZ / 4 / 256, 7);
        wround_all<<<grid, 256>>>(Wq, Wk, Wv, Wo, W1, W2, Wsep, wr, WTSZ / 4);
    }

    EncParams p;
    p.wr = wr;
    p.bq = bq; p.bk = bk; p.bv = bv; p.bo = bo;
    p.ln1g = ln1g; p.ln1b = ln1b; p.b1 = b1; p.b2 = b2; p.ln2g = ln2g; p.ln2b = ln2b;

    // ---- launch 2: main embed; launch 3: image projection (independent) ----
    embed_kernel<<<MAIN_TOK, 128>>>(segment, embedding, x, SLEN);
    gemm(sep_img, wr + (size_t)6 * WTSZ, bsep, sep, HIST_SEQ, FFDIM, IMGDIM, 0);
    // launches 4,5,6: Wq, Wk, Wv GEMMs of layer 0 (ncu -s 5 captures #6)

    // ---- main encoder ----
    run_encoder(x, q, k, v, t1, t2, p, nullptr, BATCH, SLEN);
    copy_hidden_kernel<<<BATCH, 128>>>(x, hid);

    // ---- history encoder ----
    embed_kernel<<<HIST_TOK, 128>>>(prev_hist, embedding, x, TLEN);
    run_encoder(x, q, k, v, t1, t2, p, hist_len, HIST_SEQ, TLEN);

    // ---- gather last hidden, add to sep, normalize + dot ----
    gather_add_kernel<<<HIST_SEQ, 128>>>(x, hist_len, sep);
    final_kernel<<<HIST_SEQ, 128>>>(sep, hid, normalize, (float*)d_out);
}